// round 2
// baseline (speedup 1.0000x reference)
#include <cuda_runtime.h>

#define S3 0.86602540378443864676f   // sqrt(3)/2

// ---------------- scratch (no allocation allowed) ----------------
__device__ float2 g_A[8*32*16*3*128];   // [bi][kx][p][t]   x-DFT output
__device__ float2 g_X[1024*256];        // [mode][b*32+i]   forward modes
__device__ float2 g_W[1024*1024];       // [mode][i*32+o]   transposed weights
__device__ float2 g_Y[8*32*16*32*2];    // [bo][kx][kt][kz] mixed modes
__device__ float2 g_V[8*32*128*16*3];   // [bo][t][kx][p]   t-expanded

// ---------------- k0: weight transpose -> per-mode [i][o] complex ----------
__global__ void k0_wt(const float* __restrict__ w1re, const float* __restrict__ w1im,
                      const float* __restrict__ w2re, const float* __restrict__ w2im) {
    int mode = blockIdx.x;                 // ((kt*16)+kx)*2+kz
    int kz = mode & 1, kx = (mode >> 1) & 15, kt = mode >> 5;
    const float* wre; const float* wim; int ktw;
    if (kt < 16) { wre = w1re; wim = w1im; ktw = kt; }
    else         { wre = w2re; wim = w2im; ktw = kt - 16; }
    for (int r = threadIdx.x; r < 1024; r += 256) {
        int i = r >> 5, o = r & 31;
        int src = (((i*32 + o)*16 + ktw)*16 + kx)*3 + kz;
        g_W[mode*1024 + r] = make_float2(wre[src], wim[src]);
    }
}

// ---------------- k1: x-DFT (256 -> 16 modes), real input -----------------
// block = one (b,i, t-pair); 96 threads: tl(2) x kx(16) x p(3)
__global__ void k1_xdft(const float* __restrict__ x) {
    __shared__ float  xs[1536];
    __shared__ float2 tab[256];
    int blk = blockIdx.x, tid = threadIdx.x;
    int bi = blk >> 6, tp = blk & 63;
    const float* src = x + (size_t)(bi*128 + tp*2) * 768;
    for (int i = tid; i < 1536; i += 96) xs[i] = src[i];
    for (int j = tid; j < 256; j += 96) {
        float s, c; sincospif(j * (1.0f/128.0f), &s, &c);
        tab[j] = make_float2(c, s);
    }
    __syncthreads();
    int tl = tid / 48, r = tid % 48;
    int kx = r & 15, p = r >> 4;
    const float* row = xs + tl*768 + p;
    float re = 0.f, im = 0.f;
    int j = 0;
    #pragma unroll 8
    for (int xi = 0; xi < 256; xi++) {
        float v = row[xi*3];
        float2 cs = tab[j];
        re += v * cs.x;          // e^{-i theta}: re = sum x*cos
        im -= v * cs.y;          //              im = -sum x*sin
        j = (j + kx) & 255;
    }
    g_A[((bi*16 + kx)*3 + p)*128 + (tp*2 + tl)] = make_float2(re, im);
}

// ---------------- k2: t-DFT (128 -> 32 modes) + p-rfft (3 -> 2) -----------
// block = (b,i,kx); 96 threads: kt(32) x p(3)
__global__ void k2_tdft() {
    __shared__ float2 As[384];
    __shared__ float2 tab[128];
    __shared__ float2 Xt[32][3];
    int blk = blockIdx.x, tid = threadIdx.x;
    int bi = blk >> 4, kx = blk & 15;
    const float2* src = g_A + (size_t)(bi*16 + kx)*384;
    for (int i = tid; i < 384; i += 96) As[i] = src[i];
    for (int j = tid; j < 128; j += 96) {
        float s, c; sincospif(j * (1.0f/64.0f), &s, &c);
        tab[j] = make_float2(c, s);
    }
    __syncthreads();
    int kt = tid & 31, p = tid >> 5;
    int ktg = kt + (kt >= 16 ? 96 : 0);    // global mode 0..15 / 112..127
    float re = 0.f, im = 0.f;
    int j = 0;
    #pragma unroll 8
    for (int t = 0; t < 128; t++) {
        float2 a = As[p*128 + t];
        float2 cs = tab[j];
        re += a.x*cs.x + a.y*cs.y;   // (a)(c - i s)
        im += a.y*cs.x - a.x*cs.y;
        j = (j + ktg) & 127;
    }
    Xt[kt][p] = make_float2(re, im);
    __syncthreads();
    if (tid < 64) {
        int kt2 = tid & 31, kz = tid >> 5;
        float2 a0 = Xt[kt2][0], a1 = Xt[kt2][1], a2 = Xt[kt2][2];
        float2 rr;
        if (kz == 0) rr = make_float2(a0.x + a1.x + a2.x, a0.y + a1.y + a2.y);
        else rr = make_float2(a0.x - 0.5f*(a1.x + a2.x) + S3*(a1.y - a2.y),
                              a0.y - 0.5f*(a1.y + a2.y) - S3*(a1.x - a2.x));
        g_X[((kt2*16 + kx)*2 + kz)*256 + bi] = rr;
    }
}

// ---------------- k3: per-mode complex GEMM Y[b,o] = sum_i X[b,i] W[i,o] --
__global__ void k3_mix() {
    __shared__ float2 Xs[256];
    __shared__ float2 Ws[1024];
    int mode = blockIdx.x, tid = threadIdx.x;
    Xs[tid] = g_X[mode*256 + tid];
    #pragma unroll
    for (int k = 0; k < 4; k++) Ws[tid + k*256] = g_W[(size_t)mode*1024 + tid + k*256];
    __syncthreads();
    int b = tid >> 5, o = tid & 31;
    float re = 0.f, im = 0.f;
    #pragma unroll
    for (int i = 0; i < 32; i++) {
        float2 xv = Xs[b*32 + i];
        float2 wv = Ws[i*32 + o];
        re += xv.x*wv.x - xv.y*wv.y;
        im += xv.x*wv.y + xv.y*wv.x;
    }
    int kz = mode & 1, kx = (mode >> 1) & 15, kt = mode >> 5;
    g_Y[(((b*32 + o)*16 + kx)*32 + kt)*2 + kz] = make_float2(re, im);
}

// ---------------- k4: build U_p, expand kt -> t (32 -> 128) ---------------
// block = (bo, kx); 384 threads: t(128) x p(3)
__global__ void k4_texp() {
    __shared__ float2 Ys[64];
    __shared__ float2 U[96];      // [kt*3+p]
    __shared__ float2 tab[128];
    int blk = blockIdx.x, tid = threadIdx.x;
    int bo = blk >> 4, kx = blk & 15;
    if (tid < 64) Ys[tid] = g_Y[(bo*16 + kx)*64 + tid];
    if (tid >= 256) {
        int j = tid - 256;
        float s, c; sincospif(j * (1.0f/64.0f), &s, &c);
        tab[j] = make_float2(c, s);
    }
    __syncthreads();
    if (tid < 96) {
        int kt = tid & 31, p = tid >> 5;
        float2 y0 = Ys[kt*2], y1 = Ys[kt*2 + 1];
        float wx, wy;                         // 2 * e^{2 pi i p / 3}
        if (p == 0)      { wx = 2.f;  wy = 0.f; }
        else if (p == 1) { wx = -1.f; wy =  2.f*S3; }
        else             { wx = -1.f; wy = -2.f*S3; }
        const float SC = 1.f/98304.f;         // 1/(128*256*3)
        U[kt*3 + p] = make_float2(SC*(y0.x + wx*y1.x - wy*y1.y),
                                  SC*(y0.y + wx*y1.y + wy*y1.x));
    }
    __syncthreads();
    int t = tid & 127, p = tid >> 7;
    float re = 0.f, im = 0.f;
    int j = 0;
    #pragma unroll
    for (int kt = 0; kt < 16; kt++) {         // global modes kt
        float2 u = U[kt*3 + p]; float2 cs = tab[j];
        re += u.x*cs.x - u.y*cs.y;            // (u)(c + i s)
        im += u.x*cs.y + u.y*cs.x;
        j = (j + t) & 127;
    }
    j = (112 * t) & 127;                       // global modes 112..127
    #pragma unroll
    for (int kt = 16; kt < 32; kt++) {
        float2 u = U[kt*3 + p]; float2 cs = tab[j];
        re += u.x*cs.x - u.y*cs.y;
        im += u.x*cs.y + u.y*cs.x;
        j = (j + t) & 127;
    }
    g_V[((bo*128 + t)*16 + kx)*3 + p] = make_float2(re, im);
}

// ---------------- k5: expand kx -> x (16 -> 256), take Re, store ----------
// block = (bo, t); 256 threads = x
__global__ void k5_xexp(float* __restrict__ out) {
    __shared__ float2 Vs[48];
    __shared__ float2 tab[256];
    int blk = blockIdx.x, tid = threadIdx.x;
    if (tid < 48) Vs[tid] = g_V[(size_t)blk*48 + tid];
    {
        float s, c; sincospif(tid * (1.0f/128.0f), &s, &c);
        tab[tid] = make_float2(c, s);
    }
    __syncthreads();
    int x = tid;
    float a0 = 0.f, a1 = 0.f, a2 = 0.f;
    int j = 0;
    #pragma unroll
    for (int kx = 0; kx < 16; kx++) {
        float2 cs = tab[j];
        float2 v0 = Vs[kx*3], v1 = Vs[kx*3+1], v2 = Vs[kx*3+2];
        a0 += v0.x*cs.x - v0.y*cs.y;   // Re( V * e^{+i theta} )
        a1 += v1.x*cs.x - v1.y*cs.y;
        a2 += v2.x*cs.x - v2.y*cs.y;
        j = (j + x) & 255;
    }
    float* dst = out + (size_t)blk*768 + x*3;
    dst[0] = a0; dst[1] = a1; dst[2] = a2;
}

extern "C" void kernel_launch(void* const* d_in, const int* in_sizes, int n_in,
                              void* d_out, int out_size) {
    const float* x    = (const float*)d_in[0];
    const float* w1re = (const float*)d_in[1];
    const float* w1im = (const float*)d_in[2];
    const float* w2re = (const float*)d_in[3];
    const float* w2im = (const float*)d_in[4];
    float* out = (float*)d_out;

    k0_wt <<<1024,  256>>>(w1re, w1im, w2re, w2im);
    k1_xdft<<<16384, 96>>>(x);
    k2_tdft<<<4096,  96>>>();
    k3_mix <<<1024,  256>>>();
    k4_texp<<<4096,  384>>>();
    k5_xexp<<<32768, 256>>>(out);
}

// round 3
// speedup vs baseline: 1.9048x; 1.9048x over previous
#include <cuda_runtime.h>

#define S3 0.86602540378443864676f   // sqrt(3)/2

// ---------------- scratch ----------------
__device__ float2 g_A[8*32*16*3*128];   // [bi][kx][p][t]
__device__ float2 g_X[1024*256];        // [mode][b*32+i]
__device__ float2 g_W[1024*1024];       // [mode][i*32+o]
__device__ float2 g_Y[8*32*16*32*2];    // [bo][kx][kt][kz]
__device__ float2 g_V[8*32*128*16*3];   // [bo][t][kx][p]
// twiddle tables, consumer-native layouts (raw cos,sin)
__device__ float2 g_T1[256*16];         // [xi][kx]   th = 2pi xi kx/256
__device__ float2 g_T2[128*32];         // [t][kt]    ph = 2pi t ktg/128
__device__ float2 g_T2T[32*128];        // [kt][t]
__device__ float2 g_T5[16*256];         // [kx][x]    th = 2pi x kx/256

// ---------------- k0: weights (coalesced reads) + tables ------------------
__global__ void k0_prep(const float* __restrict__ w1re, const float* __restrict__ w1im,
                        const float* __restrict__ w2re, const float* __restrict__ w2im) {
    int blk = blockIdx.x, tid = threadIdx.x;
    if (blk < 1024) {
        int io = blk;                         // i*32 + o
        for (int e = tid; e < 512; e += 256) {
            int kz = e & 1, kx = (e >> 1) & 15, ktw = e >> 5;
            int s = io*768 + (ktw*16 + kx)*3 + kz;
            int m1 = (ktw*16 + kx)*2 + kz;            // kt = ktw
            int m2 = ((ktw + 16)*16 + kx)*2 + kz;     // kt = ktw+16 (high modes)
            g_W[(size_t)m1*1024 + io] = make_float2(w1re[s], w1im[s]);
            g_W[(size_t)m2*1024 + io] = make_float2(w2re[s], w2im[s]);
        }
    } else if (blk == 1024) {
        for (int i = tid; i < 4096; i += 256) {
            int xi = i >> 4, kx = i & 15;
            float s, c; sincospif((float)(xi*kx) * (1.0f/128.0f), &s, &c);
            g_T1[i] = make_float2(c, s);
        }
    } else if (blk == 1025) {
        for (int i = tid; i < 4096; i += 256) {
            int t = i >> 5, kt = i & 31;
            int ktg = kt + ((kt >= 16) ? 96 : 0);
            float s, c; sincospif((float)(t*ktg) * (1.0f/64.0f), &s, &c);
            g_T2[t*32 + kt]   = make_float2(c, s);
            g_T2T[kt*128 + t] = make_float2(c, s);
        }
    } else {
        for (int i = tid; i < 4096; i += 256) {
            int kx = i >> 8, xx = i & 255;
            float s, c; sincospif((float)(xx*kx) * (1.0f/128.0f), &s, &c);
            g_T5[i] = make_float2(c, s);
        }
    }
}

// ---------------- k1: x-DFT (256 -> 16 modes), conflict-free --------------
// grid 4096 = (bi, 8-t chunk); block 128 = (kx 16) x (t 8); 3 p folded/thread
__global__ void k1_xdft(const float* __restrict__ x) {
    __shared__ float xs[8*769];            // pitch 769 -> conflict-free
    int blk = blockIdx.x, tid = threadIdx.x;
    int bi = blk >> 4, tc = blk & 15;
    const float* src = x + ((size_t)bi*128 + tc*8) * 768;
    for (int idx = tid; idx < 8*768; idx += 128) {
        int t = idx / 768, j = idx - t*768;
        xs[t*769 + j] = src[idx];
    }
    __syncthreads();
    int kx = tid >> 3, ts = tid & 7;
    const float* row = xs + ts*769;
    float r0=0,i0=0,r1=0,i1=0,r2=0,i2=0;
    #pragma unroll 4
    for (int xi = 0; xi < 256; xi++) {
        float2 T = __ldg(&g_T1[xi*16 + kx]);       // e^{-i th}: (c, s)
        float v0 = row[xi*3+0], v1 = row[xi*3+1], v2 = row[xi*3+2];
        r0 += v0*T.x; i0 -= v0*T.y;
        r1 += v1*T.x; i1 -= v1*T.y;
        r2 += v2*T.x; i2 -= v2*T.y;
    }
    size_t base = (size_t)(bi*16 + kx)*384 + (tc*8 + ts);
    g_A[base      ] = make_float2(r0, i0);
    g_A[base + 128] = make_float2(r1, i1);
    g_A[base + 256] = make_float2(r2, i2);
}

// ---------------- k2: t-DFT (128 -> 32 modes) + p-rfft (3 -> 2) -----------
// grid 4096 = (bi, kx); block 96 = (kt 32) x (p 3)
__global__ void k2_tdft() {
    __shared__ float2 As[384];
    __shared__ float2 Xt[32][3];
    int blk = blockIdx.x, tid = threadIdx.x;
    int bi = blk >> 4, kx = blk & 15;
    const float2* src = g_A + (size_t)(bi*16 + kx)*384;
    for (int i = tid; i < 384; i += 96) As[i] = src[i];
    __syncthreads();
    int kt = tid & 31, p = tid >> 5;
    const float2* Ap = As + p*128;
    float re = 0.f, im = 0.f;
    #pragma unroll 4
    for (int t = 0; t < 128; t++) {
        float2 a = Ap[t];
        float2 cs = __ldg(&g_T2[t*32 + kt]);       // a * e^{-i ph}
        re += a.x*cs.x + a.y*cs.y;
        im += a.y*cs.x - a.x*cs.y;
    }
    Xt[kt][p] = make_float2(re, im);
    __syncthreads();
    if (tid < 64) {
        int kt2 = tid & 31, kz = tid >> 5;
        float2 a0 = Xt[kt2][0], a1 = Xt[kt2][1], a2 = Xt[kt2][2];
        float2 rr;
        if (kz == 0) rr = make_float2(a0.x + a1.x + a2.x, a0.y + a1.y + a2.y);
        else rr = make_float2(a0.x - 0.5f*(a1.x + a2.x) + S3*(a1.y - a2.y),
                              a0.y - 0.5f*(a1.y + a2.y) - S3*(a1.x - a2.x));
        g_X[(size_t)((kt2*16 + kx)*2 + kz)*256 + bi] = rr;
    }
}

// ---------------- k3: per-mode complex GEMM Y[b,o] = sum_i X[b,i] W[i,o] --
__global__ void k3_mix() {
    __shared__ float2 Xs[256];
    __shared__ float2 Ws[1024];
    int mode = blockIdx.x, tid = threadIdx.x;
    Xs[tid] = g_X[(size_t)mode*256 + tid];
    #pragma unroll
    for (int k = 0; k < 4; k++) Ws[tid + k*256] = g_W[(size_t)mode*1024 + tid + k*256];
    __syncthreads();
    int b = tid >> 5, o = tid & 31;
    float re = 0.f, im = 0.f;
    #pragma unroll
    for (int i = 0; i < 32; i++) {
        float2 xv = Xs[b*32 + i];
        float2 wv = Ws[i*32 + o];
        re += xv.x*wv.x - xv.y*wv.y;
        im += xv.x*wv.y + xv.y*wv.x;
    }
    int kz = mode & 1, kx = (mode >> 1) & 15, kt = mode >> 5;
    g_Y[(size_t)(((b*32 + o)*16 + kx)*32 + kt)*2 + kz] = make_float2(re, im);
}

// ---------------- k4: build U_p, expand kt -> t (32 -> 128) ---------------
// grid 4096 = (bo, kx); block 384 = (t 128) x (p 3)
__global__ void k4_texp() {
    __shared__ float2 Ys[64];
    __shared__ float2 U[96];
    int blk = blockIdx.x, tid = threadIdx.x;
    int bo = blk >> 4, kx = blk & 15;
    if (tid < 64) Ys[tid] = g_Y[(size_t)(bo*16 + kx)*64 + tid];
    __syncthreads();
    if (tid < 96) {
        int kt = tid & 31, p = tid >> 5;
        float2 y0 = Ys[kt*2], y1 = Ys[kt*2 + 1];
        float wx, wy;                          // 2 * e^{2 pi i p / 3}
        if (p == 0)      { wx = 2.f;  wy = 0.f; }
        else if (p == 1) { wx = -1.f; wy =  2.f*S3; }
        else             { wx = -1.f; wy = -2.f*S3; }
        const float SC = 1.f/98304.f;          // 1/(128*256*3)
        U[kt*3 + p] = make_float2(SC*(y0.x + wx*y1.x - wy*y1.y),
                                  SC*(y0.y + wx*y1.y + wy*y1.x));
    }
    __syncthreads();
    int t = tid & 127, p = tid >> 7;
    float re = 0.f, im = 0.f;
    #pragma unroll 8
    for (int kt = 0; kt < 32; kt++) {
        float2 u = U[kt*3 + p];
        float2 cs = __ldg(&g_T2T[kt*128 + t]);  // u * e^{+i ph}
        re += u.x*cs.x - u.y*cs.y;
        im += u.x*cs.y + u.y*cs.x;
    }
    g_V[(size_t)((bo*128 + t)*16 + kx)*3 + p] = make_float2(re, im);
}

// ---------------- k5: expand kx -> x (16 -> 256), take Re, store ----------
// grid 32768 = (bo, t); block 256 = x
__global__ void k5_xexp(float* __restrict__ out) {
    __shared__ float2 Vs[48];
    int blk = blockIdx.x, tid = threadIdx.x;
    if (tid < 48) Vs[tid] = g_V[(size_t)blk*48 + tid];
    __syncthreads();
    int x = tid;
    float a0 = 0.f, a1 = 0.f, a2 = 0.f;
    #pragma unroll
    for (int kx = 0; kx < 16; kx++) {
        float2 cs = __ldg(&g_T5[kx*256 + x]);   // Re(V e^{+i th})
        float2 v0 = Vs[kx*3], v1 = Vs[kx*3+1], v2 = Vs[kx*3+2];
        a0 += v0.x*cs.x - v0.y*cs.y;
        a1 += v1.x*cs.x - v1.y*cs.y;
        a2 += v2.x*cs.x - v2.y*cs.y;
    }
    float* dst = out + (size_t)blk*768 + x*3;
    dst[0] = a0; dst[1] = a1; dst[2] = a2;
}

extern "C" void kernel_launch(void* const* d_in, const int* in_sizes, int n_in,
                              void* d_out, int out_size) {
    const float* x    = (const float*)d_in[0];
    const float* w1re = (const float*)d_in[1];
    const float* w1im = (const float*)d_in[2];
    const float* w2re = (const float*)d_in[3];
    const float* w2im = (const float*)d_in[4];
    float* out = (float*)d_out;

    k0_prep<<<1027,  256>>>(w1re, w1im, w2re, w2im);
    k1_xdft<<<4096,  128>>>(x);
    k2_tdft<<<4096,   96>>>();
    k3_mix <<<1024,  256>>>();
    k4_texp<<<4096,  384>>>();
    k5_xexp<<<32768, 256>>>(out);
}

// round 4
// speedup vs baseline: 2.6142x; 1.3724x over previous
#include <cuda_runtime.h>

#define S3 0.86602540378443864676f   // sqrt(3)/2

// ---------------- scratch ----------------
__device__ float2 g_A[8*32*16*3*128];   // [bi][kx][p][t]
__device__ float2 g_X[1024*256];        // [mode][b*32+i]
__device__ float2 g_W[1024*1024];       // [mode][i*32+o]
__device__ float2 g_Y[8*32*16*32*2];    // [bo][kx][kt][kz]
__device__ float2 g_V[8*32*128*16*3];   // [bo][t][kx][p]
// twiddle tables (folded, consumer-native layouts)
__device__ float2 g_T1[128*16];         // [xi<128][kx]  th = 2pi xi kx/256
__device__ float2 g_T2[64*32];          // [t<64][kt]    ph = 2pi t ktg/128
__device__ float2 g_T4[32*64];          // [kt][t<64]
__device__ float2 g_T5[16*128];         // [kx][x<128]   th = 2pi x kx/256

// ---------------- k0: weights (coalesced reads) + tables ------------------
__global__ void k0_prep(const float* __restrict__ w1re, const float* __restrict__ w1im,
                        const float* __restrict__ w2re, const float* __restrict__ w2im) {
    int blk = blockIdx.x, tid = threadIdx.x;
    if (blk < 1024) {
        int io = blk;                         // i*32 + o
        for (int e = tid; e < 512; e += 256) {
            int kz = e & 1, kx = (e >> 1) & 15, ktw = e >> 5;
            int s = io*768 + (ktw*16 + kx)*3 + kz;
            int m1 = (ktw*16 + kx)*2 + kz;            // kt = ktw
            int m2 = ((ktw + 16)*16 + kx)*2 + kz;     // kt = ktw+16 (high modes)
            g_W[(size_t)m1*1024 + io] = make_float2(w1re[s], w1im[s]);
            g_W[(size_t)m2*1024 + io] = make_float2(w2re[s], w2im[s]);
        }
    } else if (blk == 1024) {
        for (int i = tid; i < 2048; i += 256) {
            int xi = i >> 4, kx = i & 15;
            float s, c; sincospif((float)(xi*kx) * (1.0f/128.0f), &s, &c);
            g_T1[i] = make_float2(c, s);
        }
    } else if (blk == 1025) {
        for (int i = tid; i < 2048; i += 256) {
            int t = i >> 5, kt = i & 31;
            int ktg = kt + ((kt >= 16) ? 96 : 0);
            float s, c; sincospif((float)(t*ktg) * (1.0f/64.0f), &s, &c);
            g_T2[i] = make_float2(c, s);
        }
    } else if (blk == 1026) {
        for (int i = tid; i < 2048; i += 256) {
            int kt = i >> 6, t = i & 63;
            int ktg = kt + ((kt >= 16) ? 96 : 0);
            float s, c; sincospif((float)(t*ktg) * (1.0f/64.0f), &s, &c);
            g_T4[i] = make_float2(c, s);
        }
    } else {
        for (int i = tid; i < 2048; i += 256) {
            int kx = i >> 7, xx = i & 127;
            float s, c; sincospif((float)(xx*kx) * (1.0f/128.0f), &s, &c);
            g_T5[i] = make_float2(c, s);
        }
    }
}

// ---------------- k1: x-DFT (256 -> 16 modes), radix-2 folded -------------
// grid 4096 = (bi, 8-t chunk); block 128 = (kx 16) x (t 8)
__global__ void k1_xdft(const float* __restrict__ x) {
    __shared__ float xe[8*385];            // e = x[xi]+x[xi+128], pitch 385
    __shared__ float xo[8*385];            // o = x[xi]-x[xi+128]
    int blk = blockIdx.x, tid = threadIdx.x;
    int bi = blk >> 4, tc = blk & 15;
    const float* src = x + ((size_t)bi*128 + tc*8) * 768;
    #pragma unroll
    for (int t = 0; t < 8; t++) {
        for (int j = tid; j < 384; j += 128) {
            float a = src[t*768 + j], b = src[t*768 + 384 + j];
            xe[t*385 + j] = a + b;
            xo[t*385 + j] = a - b;
        }
    }
    __syncthreads();
    int kx = tid >> 3, ts = tid & 7;
    const float* row = ((kx & 1) ? xo : xe) + ts*385;
    float r0=0,i0=0,r1=0,i1=0,r2=0,i2=0;
    #pragma unroll 4
    for (int xi = 0; xi < 128; xi++) {
        float2 T = __ldg(&g_T1[xi*16 + kx]);       // e^{-i th}: (c, s)
        float v0 = row[xi*3+0], v1 = row[xi*3+1], v2 = row[xi*3+2];
        r0 += v0*T.x; i0 -= v0*T.y;
        r1 += v1*T.x; i1 -= v1*T.y;
        r2 += v2*T.x; i2 -= v2*T.y;
    }
    size_t base = (size_t)(bi*16 + kx)*384 + (tc*8 + ts);
    g_A[base      ] = make_float2(r0, i0);
    g_A[base + 128] = make_float2(r1, i1);
    g_A[base + 256] = make_float2(r2, i2);
}

// ---------------- k2: t-DFT (128 -> 32 modes) folded + p-rfft (3 -> 2) ----
// grid 4096 = (bi, kx); block 96 = (kt 32) x (p 3)
__global__ void k2_tdft() {
    __shared__ float2 As[384];
    __shared__ float2 Es[192], Os[192];    // [p][t<64]
    __shared__ float2 Xt[32][3];
    int blk = blockIdx.x, tid = threadIdx.x;
    int bi = blk >> 4, kx = blk & 15;
    const float2* src = g_A + (size_t)(bi*16 + kx)*384;
    for (int i = tid; i < 384; i += 96) As[i] = src[i];
    __syncthreads();
    for (int i = tid; i < 192; i += 96) {
        int p = i >> 6, t = i & 63;
        float2 a = As[p*128 + t], b = As[p*128 + t + 64];
        Es[i] = make_float2(a.x + b.x, a.y + b.y);
        Os[i] = make_float2(a.x - b.x, a.y - b.y);
    }
    __syncthreads();
    int kt = tid & 31, p = tid >> 5;
    const float2* Ap = ((kt & 1) ? Os : Es) + p*64;
    float re = 0.f, im = 0.f;
    #pragma unroll 4
    for (int t = 0; t < 64; t++) {
        float2 a = Ap[t];
        float2 cs = __ldg(&g_T2[t*32 + kt]);       // a * e^{-i ph}
        re += a.x*cs.x + a.y*cs.y;
        im += a.y*cs.x - a.x*cs.y;
    }
    Xt[kt][p] = make_float2(re, im);
    __syncthreads();
    if (tid < 64) {
        int kt2 = tid & 31, kz = tid >> 5;
        float2 a0 = Xt[kt2][0], a1 = Xt[kt2][1], a2 = Xt[kt2][2];
        float2 rr;
        if (kz == 0) rr = make_float2(a0.x + a1.x + a2.x, a0.y + a1.y + a2.y);
        else rr = make_float2(a0.x - 0.5f*(a1.x + a2.x) + S3*(a1.y - a2.y),
                              a0.y - 0.5f*(a1.y + a2.y) - S3*(a1.x - a2.x));
        g_X[(size_t)((kt2*16 + kx)*2 + kz)*256 + bi] = rr;
    }
}

// ---------------- k3: per-mode complex GEMM Y[b,o] = sum_i X[b,i] W[i,o] --
__global__ void k3_mix() {
    __shared__ float2 Xs[256];
    __shared__ float2 Ws[1024];
    int mode = blockIdx.x, tid = threadIdx.x;
    Xs[tid] = g_X[(size_t)mode*256 + tid];
    const float4* wsrc = (const float4*)(g_W + (size_t)mode*1024);
    float4* wdst = (float4*)Ws;
    wdst[tid]       = wsrc[tid];
    wdst[tid + 256] = wsrc[tid + 256];
    __syncthreads();
    int b = tid >> 5, o = tid & 31;
    float re0=0, im0=0, re1=0, im1=0;
    #pragma unroll
    for (int i = 0; i < 32; i += 2) {
        float2 xv = Xs[b*32 + i];     float2 wv = Ws[i*32 + o];
        re0 += xv.x*wv.x - xv.y*wv.y; im0 += xv.x*wv.y + xv.y*wv.x;
        float2 xq = Xs[b*32 + i + 1]; float2 wq = Ws[(i+1)*32 + o];
        re1 += xq.x*wq.x - xq.y*wq.y; im1 += xq.x*wq.y + xq.y*wq.x;
    }
    int kz = mode & 1, kx = (mode >> 1) & 15, kt = mode >> 5;
    g_Y[(size_t)(((b*32 + o)*16 + kx)*32 + kt)*2 + kz] = make_float2(re0+re1, im0+im1);
}

// ---------------- k4: build U_p, expand kt -> t (folded, 2 t per thread) --
// grid 4096 = (bo, kx); block 192 = (t 64) x (p 3)
__global__ void k4_texp() {
    __shared__ float2 Ys[64];
    __shared__ float2 U[96];
    int blk = blockIdx.x, tid = threadIdx.x;
    int bo = blk >> 4, kx = blk & 15;
    if (tid < 64) Ys[tid] = g_Y[(size_t)(bo*16 + kx)*64 + tid];
    __syncthreads();
    if (tid < 96) {
        int kt = tid & 31, p = tid >> 5;
        float2 y0 = Ys[kt*2], y1 = Ys[kt*2 + 1];
        float wx, wy;                          // 2 * e^{2 pi i p / 3}
        if (p == 0)      { wx = 2.f;  wy = 0.f; }
        else if (p == 1) { wx = -1.f; wy =  2.f*S3; }
        else             { wx = -1.f; wy = -2.f*S3; }
        const float SC = 1.f/98304.f;          // 1/(128*256*3)
        U[kt*3 + p] = make_float2(SC*(y0.x + wx*y1.x - wy*y1.y),
                                  SC*(y0.y + wx*y1.y + wy*y1.x));
    }
    __syncthreads();
    int t = tid & 63, p = tid >> 6;
    float ser=0, sei=0, sor=0, soi=0;
    #pragma unroll
    for (int kt = 0; kt < 32; kt++) {
        float2 u = U[kt*3 + p];
        float2 cs = __ldg(&g_T4[kt*64 + t]);    // u * e^{+i ph}
        float tr = u.x*cs.x - u.y*cs.y;
        float ti = u.x*cs.y + u.y*cs.x;
        if ((kt & 1) == 0) { ser += tr; sei += ti; }
        else               { sor += tr; soi += ti; }
    }
    size_t i0 = (size_t)(bo*128 + t)*48      + kx*3 + p;
    size_t i1 = (size_t)(bo*128 + t + 64)*48 + kx*3 + p;
    g_V[i0] = make_float2(ser + sor, sei + soi);   // V(t)
    g_V[i1] = make_float2(ser - sor, sei - soi);   // V(t+64)
}

// ---------------- k5: expand kx -> x (folded, 2 x per thread), Re, store --
// grid 16384 = (bo, t-pair); block 256 = (tl 2) x (x 128)
__global__ void k5_xexp(float* __restrict__ out) {
    __shared__ float2 Vs[2][48];
    int blk = blockIdx.x, tid = threadIdx.x;
    int bo = blk >> 6, tp = blk & 63;
    if (tid < 96) {
        int tl = tid / 48, i = tid % 48;
        Vs[tl][i] = g_V[(size_t)(bo*128 + tp*2 + tl)*48 + i];
    }
    __syncthreads();
    int tl = tid >> 7, xl = tid & 127;
    const float2* V = Vs[tl];
    float se0=0,se1=0,se2=0, so0=0,so1=0,so2=0;
    #pragma unroll
    for (int kx = 0; kx < 16; kx++) {
        float2 cs = __ldg(&g_T5[kx*128 + xl]);  // Re(V e^{+i th})
        float2 v0 = V[kx*3], v1 = V[kx*3+1], v2 = V[kx*3+2];
        float t0 = v0.x*cs.x - v0.y*cs.y;
        float t1 = v1.x*cs.x - v1.y*cs.y;
        float t2 = v2.x*cs.x - v2.y*cs.y;
        if (kx & 1) { so0 += t0; so1 += t1; so2 += t2; }
        else        { se0 += t0; se1 += t1; se2 += t2; }
    }
    float* dst = out + (size_t)(bo*128 + tp*2 + tl)*768;
    dst[xl*3 + 0] = se0 + so0;
    dst[xl*3 + 1] = se1 + so1;
    dst[xl*3 + 2] = se2 + so2;
    dst[(xl+128)*3 + 0] = se0 - so0;
    dst[(xl+128)*3 + 1] = se1 - so1;
    dst[(xl+128)*3 + 2] = se2 - so2;
}

extern "C" void kernel_launch(void* const* d_in, const int* in_sizes, int n_in,
                              void* d_out, int out_size) {
    const float* x    = (const float*)d_in[0];
    const float* w1re = (const float*)d_in[1];
    const float* w1im = (const float*)d_in[2];
    const float* w2re = (const float*)d_in[3];
    const float* w2im = (const float*)d_in[4];
    float* out = (float*)d_out;

    k0_prep<<<1028,  256>>>(w1re, w1im, w2re, w2im);
    k1_xdft<<<4096,  128>>>(x);
    k2_tdft<<<4096,   96>>>();
    k3_mix <<<1024,  256>>>();
    k4_texp<<<4096,  192>>>();
    k5_xexp<<<16384, 256>>>(out);
}

// round 5
// speedup vs baseline: 2.9703x; 1.1362x over previous
#include <cuda_runtime.h>

#define S3 0.86602540378443864676f   // sqrt(3)/2

// ---------------- scratch ----------------
__device__ float2 g_A[8*32*16*3*128];   // [bi][kx][p][t]
__device__ float2 g_X[1024*256];        // [mode][b*32+i]
__device__ float2 g_W[1024*1024];       // [mode][i*32+o]
__device__ float2 g_Y[8*32*16*32*2];    // [bo][kx][kt][kz]
__device__ float2 g_V[8*32*128*16*3];   // [bo][t][kx][p]
// twiddle tables (radix-4 folded)
__device__ float2 g_T1[64*16];          // [q<64][kx]   th = 2pi q kx/256
__device__ float2 g_T2[32*32];          // [q<32][kt]   ph = 2pi q ktg/128
__device__ float2 g_T4[32*32];          // [kt][q<32]
__device__ float2 g_T5[16*64];          // [kx][q<64]   th = 2pi q kx/256

// ---------------- k0: weights + tables ------------------------------------
__global__ void k0_prep(const float* __restrict__ w1re, const float* __restrict__ w1im,
                        const float* __restrict__ w2re, const float* __restrict__ w2im) {
    int blk = blockIdx.x, tid = threadIdx.x;
    if (blk < 1024) {
        int io = blk;                         // i*32 + o
        for (int e = tid; e < 512; e += 256) {
            int kz = e & 1, kx = (e >> 1) & 15, ktw = e >> 5;
            int s = io*768 + (ktw*16 + kx)*3 + kz;
            int m1 = (ktw*16 + kx)*2 + kz;
            int m2 = ((ktw + 16)*16 + kx)*2 + kz;
            g_W[(size_t)m1*1024 + io] = make_float2(w1re[s], w1im[s]);
            g_W[(size_t)m2*1024 + io] = make_float2(w2re[s], w2im[s]);
        }
    } else if (blk == 1024) {
        for (int i = tid; i < 1024; i += 256) {
            int q = i >> 4, kx = i & 15;
            float s, c; sincospif((float)(q*kx) * (1.0f/128.0f), &s, &c);
            g_T1[i] = make_float2(c, s);
        }
    } else if (blk == 1025) {
        for (int i = tid; i < 1024; i += 256) {
            int q = i >> 5, kt = i & 31;
            int ktg = kt + ((kt >= 16) ? 96 : 0);
            float s, c; sincospif((float)(q*ktg) * (1.0f/64.0f), &s, &c);
            g_T2[i] = make_float2(c, s);
        }
    } else if (blk == 1026) {
        for (int i = tid; i < 1024; i += 256) {
            int kt = i >> 5, q = i & 31;
            int ktg = kt + ((kt >= 16) ? 96 : 0);
            float s, c; sincospif((float)(q*ktg) * (1.0f/64.0f), &s, &c);
            g_T4[i] = make_float2(c, s);
        }
    } else {
        for (int i = tid; i < 1024; i += 256) {
            int kx = i >> 6, q = i & 63;
            float s, c; sincospif((float)(q*kx) * (1.0f/128.0f), &s, &c);
            g_T5[i] = make_float2(c, s);
        }
    }
}

// ---------------- k1: x-DFT (256 -> 16 modes), radix-4 --------------------
// grid 4096 = (bi, 8-t chunk); block 128; warp w owns class c=w: kx = w+4j
__global__ void k1_xdft(const float* __restrict__ x) {
    __shared__ float e0s[8*193], e2s[8*193];     // real classes 0,2
    __shared__ float dAp[8*193], dAn[8*193];     // d02, and d13 with both signs
    __shared__ float dB [8*193];                 // d13 (raw, +)
    int blk = blockIdx.x, tid = threadIdx.x;
    int bi = blk >> 4, tc = blk & 15;
    const float* src = x + ((size_t)bi*128 + tc*8) * 768;
    for (int idx = tid; idx < 1536; idx += 128) {
        int ts = idx / 192, r = idx - ts*192;
        const float* s = src + ts*768 + r;
        float x0 = s[0], x1 = s[192], x2 = s[384], x3 = s[576];
        float s02 = x0 + x2, s13 = x1 + x3;
        e0s[ts*193 + r] = s02 + s13;
        e2s[ts*193 + r] = s02 - s13;
        dAp[ts*193 + r] = x0 - x2;      // a
        dB [ts*193 + r] = x1 - x3;      // +d13 (class 3)
        dAn[ts*193 + r] = x3 - x1;      // -d13 (class 1)
    }
    __syncthreads();
    int w = tid >> 5, lane = tid & 31;
    int j = lane >> 3, ts = lane & 7;
    int kx = w + 4*j;
    float r0=0,i0=0,r1=0,i1=0,r2=0,i2=0;
    if ((w & 1) == 0) {
        const float* row = ((w == 0) ? e0s : e2s) + ts*193;
        #pragma unroll 8
        for (int q = 0; q < 64; q++) {
            float2 T = __ldg(&g_T1[q*16 + kx]);     // e^{-i th}
            float v0 = row[q*3], v1 = row[q*3+1], v2 = row[q*3+2];
            r0 += v0*T.x; i0 -= v0*T.y;
            r1 += v1*T.x; i1 -= v1*T.y;
            r2 += v2*T.x; i2 -= v2*T.y;
        }
    } else {
        const float* ra = dAp + ts*193;
        const float* rb = ((w == 1) ? dAn : dB) + ts*193;   // b = -+d13
        #pragma unroll 4
        for (int q = 0; q < 64; q++) {
            float2 T = __ldg(&g_T1[q*16 + kx]);
            float a0 = ra[q*3], a1 = ra[q*3+1], a2 = ra[q*3+2];
            float b0 = rb[q*3], b1 = rb[q*3+1], b2 = rb[q*3+2];
            // (a+ib)(c-is) = (ac+bs) + i(bc-as)
            r0 += a0*T.x + b0*T.y;  i0 += b0*T.x - a0*T.y;
            r1 += a1*T.x + b1*T.y;  i1 += b1*T.x - a1*T.y;
            r2 += a2*T.x + b2*T.y;  i2 += b2*T.x - a2*T.y;
        }
    }
    size_t base = (size_t)(bi*16 + kx)*384 + (tc*8 + ts);
    g_A[base      ] = make_float2(r0, i0);
    g_A[base + 128] = make_float2(r1, i1);
    g_A[base + 256] = make_float2(r2, i2);
}

// ---------------- k2: t-DFT (128 -> 32 modes) radix-4 + p-rfft ------------
// grid 4096 = (bi, kx); block 96 = (kt 32) x (p 3)
__global__ void k2_tdft() {
    __shared__ float2 As[384];
    __shared__ float2 Ys[384];          // [c][p][q<32]
    __shared__ float2 Xt[32][3];
    int blk = blockIdx.x, tid = threadIdx.x;
    int bi = blk >> 4, kx = blk & 15;
    const float2* src = g_A + (size_t)(bi*16 + kx)*384;
    for (int i = tid; i < 384; i += 96) As[i] = src[i];
    __syncthreads();
    {   // build class sequences (one (p,q) per thread)
        int p = tid / 32, q = tid & 31;
        float2 A0 = As[p*128 + q], A1 = As[p*128 + q + 32];
        float2 A2 = As[p*128 + q + 64], A3 = As[p*128 + q + 96];
        float Dx = A0.x - A2.x, Dy = A0.y - A2.y;
        float Ex = A1.x - A3.x, Ey = A1.y - A3.y;
        Ys[(0*3 + p)*32 + q] = make_float2(A0.x+A1.x+A2.x+A3.x, A0.y+A1.y+A2.y+A3.y);
        Ys[(1*3 + p)*32 + q] = make_float2(Dx + Ey, Dy - Ex);   // D - iE
        Ys[(2*3 + p)*32 + q] = make_float2(A0.x-A1.x+A2.x-A3.x, A0.y-A1.y+A2.y-A3.y);
        Ys[(3*3 + p)*32 + q] = make_float2(Dx - Ey, Dy + Ex);   // D + iE
    }
    __syncthreads();
    int kt = tid & 31, p = tid >> 5;
    const float2* Yp = Ys + ((kt & 3)*3 + p)*32;
    float re = 0.f, im = 0.f;
    #pragma unroll
    for (int q = 0; q < 32; q++) {
        float2 y = Yp[q];
        float2 cs = __ldg(&g_T2[q*32 + kt]);    // y * e^{-i ph}
        re += y.x*cs.x + y.y*cs.y;
        im += y.y*cs.x - y.x*cs.y;
    }
    Xt[kt][p] = make_float2(re, im);
    __syncthreads();
    if (tid < 64) {
        int kt2 = tid & 31, kz = tid >> 5;
        float2 a0 = Xt[kt2][0], a1 = Xt[kt2][1], a2 = Xt[kt2][2];
        float2 rr;
        if (kz == 0) rr = make_float2(a0.x + a1.x + a2.x, a0.y + a1.y + a2.y);
        else rr = make_float2(a0.x - 0.5f*(a1.x + a2.x) + S3*(a1.y - a2.y),
                              a0.y - 0.5f*(a1.y + a2.y) - S3*(a1.x - a2.x));
        g_X[(size_t)((kt2*16 + kx)*2 + kz)*256 + bi] = rr;
    }
}

// ---------------- k3: per-mode complex GEMM -------------------------------
__global__ void k3_mix() {
    __shared__ float2 Xs[256];
    __shared__ float2 Ws[1024];
    int mode = blockIdx.x, tid = threadIdx.x;
    Xs[tid] = g_X[(size_t)mode*256 + tid];
    const float4* wsrc = (const float4*)(g_W + (size_t)mode*1024);
    float4* wdst = (float4*)Ws;
    wdst[tid]       = wsrc[tid];
    wdst[tid + 256] = wsrc[tid + 256];
    __syncthreads();
    int b = tid >> 5, o = tid & 31;
    float re0=0, im0=0, re1=0, im1=0;
    #pragma unroll
    for (int i = 0; i < 32; i += 2) {
        float2 xv = Xs[b*32 + i];     float2 wv = Ws[i*32 + o];
        re0 += xv.x*wv.x - xv.y*wv.y; im0 += xv.x*wv.y + xv.y*wv.x;
        float2 xq = Xs[b*32 + i + 1]; float2 wq = Ws[(i+1)*32 + o];
        re1 += xq.x*wq.x - xq.y*wq.y; im1 += xq.x*wq.y + xq.y*wq.x;
    }
    int kz = mode & 1, kx = (mode >> 1) & 15, kt = mode >> 5;
    g_Y[(size_t)(((b*32 + o)*16 + kx)*32 + kt)*2 + kz] = make_float2(re0+re1, im0+im1);
}

// ---------------- k4: build U_p, expand kt -> t radix-4 (4 t per thread) --
// grid 4096 = (bo, kx); block 96 = (q 32) x (p 3)
__global__ void k4_texp() {
    __shared__ float2 Ys[64];
    __shared__ float2 U[96];
    int blk = blockIdx.x, tid = threadIdx.x;
    int bo = blk >> 4, kx = blk & 15;
    if (tid < 64) Ys[tid] = g_Y[(size_t)(bo*16 + kx)*64 + tid];
    __syncthreads();
    {
        int kt = tid & 31, p = tid / 32;
        float2 y0 = Ys[kt*2], y1 = Ys[kt*2 + 1];
        float wx, wy;                          // 2 * e^{2 pi i p / 3}
        if (p == 0)      { wx = 2.f;  wy = 0.f; }
        else if (p == 1) { wx = -1.f; wy =  2.f*S3; }
        else             { wx = -1.f; wy = -2.f*S3; }
        const float SC = 1.f/98304.f;          // 1/(128*256*3)
        U[kt*3 + p] = make_float2(SC*(y0.x + wx*y1.x - wy*y1.y),
                                  SC*(y0.y + wx*y1.y + wy*y1.x));
    }
    __syncthreads();
    int q = tid & 31, p = tid >> 5;
    float s0x=0,s0y=0, s1x=0,s1y=0, s2x=0,s2y=0, s3x=0,s3y=0;
    #pragma unroll
    for (int kt = 0; kt < 32; kt++) {
        float2 u = U[kt*3 + p];
        float2 cs = __ldg(&g_T4[kt*32 + q]);    // u * e^{+i ph}
        float tr = u.x*cs.x - u.y*cs.y;
        float ti = u.x*cs.y + u.y*cs.x;
        switch (kt & 3) {
            case 0: s0x += tr; s0y += ti; break;
            case 1: s1x += tr; s1y += ti; break;
            case 2: s2x += tr; s2y += ti; break;
            default: s3x += tr; s3y += ti; break;
        }
    }
    size_t base = (size_t)bo*128 + q;
    size_t off = (size_t)kx*3 + p;
    // V(q+32m) = sum_c i^{mc} S_c
    g_V[(base      )*48 + off] = make_float2(s0x+s1x+s2x+s3x, s0y+s1y+s2y+s3y);
    g_V[(base + 32 )*48 + off] = make_float2(s0x-s1y-s2x+s3y, s0y+s1x-s2y-s3x);
    g_V[(base + 64 )*48 + off] = make_float2(s0x-s1x+s2x-s3x, s0y-s1y+s2y-s3y);
    g_V[(base + 96 )*48 + off] = make_float2(s0x+s1y-s2x-s3y, s0y-s1x-s2y+s3x);
}

// ---------------- k5: expand kx -> x radix-4 (4 x per thread), Re, store --
// grid 8192 = (bo, t-quad); block 256 = (tl 4) x (q 64)
__global__ void k5_xexp(float* __restrict__ out) {
    __shared__ float2 Vs[4][48];
    int blk = blockIdx.x, tid = threadIdx.x;
    int bo = blk >> 5, tq = blk & 31;
    if (tid < 192) {
        int tl = tid / 48, i = tid % 48;
        Vs[tl][i] = g_V[(size_t)(bo*128 + tq*4 + tl)*48 + i];
    }
    __syncthreads();
    int tl = tid >> 6, q = tid & 63;
    const float2* V = Vs[tl];
    // class sums: even classes need Re only; odd need full complex
    float a0x[3]={0,0,0}, a2x[3]={0,0,0};
    float a1x[3]={0,0,0}, a1y[3]={0,0,0}, a3x[3]={0,0,0}, a3y[3]={0,0,0};
    #pragma unroll
    for (int kx = 0; kx < 16; kx++) {
        float2 cs = __ldg(&g_T5[kx*64 + q]);    // e^{+i th}
        #pragma unroll
        for (int p = 0; p < 3; p++) {
            float2 v = V[kx*3 + p];
            float tr = v.x*cs.x - v.y*cs.y;
            if ((kx & 3) == 0)      a0x[p] += tr;
            else if ((kx & 3) == 2) a2x[p] += tr;
            else {
                float ti = v.x*cs.y + v.y*cs.x;
                if ((kx & 3) == 1) { a1x[p] += tr; a1y[p] += ti; }
                else               { a3x[p] += tr; a3y[p] += ti; }
            }
        }
    }
    float* dst = out + (size_t)(bo*128 + tq*4 + tl)*768;
    #pragma unroll
    for (int p = 0; p < 3; p++) {
        float e = a0x[p] + a2x[p], f = a0x[p] - a2x[p];
        dst[(q      )*3 + p] = e + a1x[p] + a3x[p];      // Re(S0+S1+S2+S3)
        dst[(q + 64 )*3 + p] = f - a1y[p] + a3y[p];      // Re(S0+iS1-S2-iS3)
        dst[(q + 128)*3 + p] = e - a1x[p] - a3x[p];
        dst[(q + 192)*3 + p] = f + a1y[p] - a3y[p];
    }
}

extern "C" void kernel_launch(void* const* d_in, const int* in_sizes, int n_in,
                              void* d_out, int out_size) {
    const float* x    = (const float*)d_in[0];
    const float* w1re = (const float*)d_in[1];
    const float* w1im = (const float*)d_in[2];
    const float* w2re = (const float*)d_in[3];
    const float* w2im = (const float*)d_in[4];
    float* out = (float*)d_out;

    k0_prep<<<1028,  256>>>(w1re, w1im, w2re, w2im);
    k1_xdft<<<4096,  128>>>(x);
    k2_tdft<<<4096,   96>>>();
    k3_mix <<<1024,  256>>>();
    k4_texp<<<4096,   96>>>();
    k5_xexp<<<8192,  256>>>(out);
}

// round 7
// speedup vs baseline: 3.0102x; 1.0134x over previous
#include <cuda_runtime.h>

#define S3 0.86602540378443864676f   // sqrt(3)/2
typedef unsigned long long u64;

__device__ __forceinline__ void ffma2(u64 &d, u64 a, u64 b) {
    asm("fma.rn.f32x2 %0, %1, %2, %0;" : "+l"(d) : "l"(a), "l"(b));
}
__device__ __forceinline__ float2 u2f(u64 v) {
    float2 f; asm("mov.b64 {%0,%1}, %2;" : "=f"(f.x), "=f"(f.y) : "l"(v)); return f;
}

// ---------------- scratch ----------------
__device__ float2 g_A[8*32*16*3*128];   // [bi][kx][p][t]
__device__ float2 g_X[1024*256];        // [mode][b*32+i]
__device__ float2 g_W[1024*1024];       // [mode][i*32+o]
__device__ float2 g_Y[8*32*16*32*2];    // [bo][kx][kt][kz]
__device__ float2 g_V[8*32*128*16*3];   // [bo][t][kx][p]
// twiddle tables
__device__ float2 g_T1cc[64*16];        // [q][kx] (c,c)   th = 2pi q kx/256
__device__ float2 g_T1ss[64*16];        // [q][kx] (s,s)
__device__ float2 g_T2[32*32];          // [q][kt] (c,s)   ph = 2pi q ktg/128
__device__ float2 g_T4[32*32];          // [kt][q] (c,s)
__device__ float2 g_T5cc[16*64];        // [kx][q] (c,c)   th = 2pi q kx/256
__device__ float2 g_T5ss[16*64];        // [kx][q] (s,s)

// ---------------- k0: tiled weight transpose + tables ---------------------
__global__ void k0_prep(const float* __restrict__ w1re, const float* __restrict__ w1im,
                        const float* __restrict__ w2re, const float* __restrict__ w2im) {
    int blk = blockIdx.x, tid = threadIdx.x;
    if (blk < 256) {
        __shared__ float2 t1[64*33], t2[64*33];
        int io0 = (blk >> 3) * 32, e0 = (blk & 7) * 64;
        int el = tid & 63, iol = tid >> 6;
        int e = e0 + el;
        int ktw = e >> 5, kx = (e >> 1) & 15, kz = e & 1;
        int off = ktw*48 + kx*3 + kz;
        #pragma unroll
        for (int pass = 0; pass < 8; pass++) {
            int il = pass*4 + iol;
            int s = (io0 + il)*768 + off;
            t1[el*33 + il] = make_float2(w1re[s], w1im[s]);
            t2[el*33 + il] = make_float2(w2re[s], w2im[s]);
        }
        __syncthreads();
        int il2 = tid & 31;
        #pragma unroll
        for (int pass = 0; pass < 8; pass++) {
            int el2 = pass*8 + (tid >> 5);
            g_W[(size_t)(e0 + el2)*1024 + io0 + il2]       = t1[el2*33 + il2];
            g_W[(size_t)(e0 + el2 + 512)*1024 + io0 + il2] = t2[el2*33 + il2];
        }
    } else if (blk == 256) {
        for (int i = tid; i < 1024; i += 256) {
            int q = i >> 4, kx = i & 15;
            float s, c; sincospif((float)(q*kx) * (1.0f/128.0f), &s, &c);
            g_T1cc[i] = make_float2(c, c);
            g_T1ss[i] = make_float2(s, s);
        }
    } else if (blk == 257) {
        for (int i = tid; i < 1024; i += 256) {
            int q = i >> 5, kt = i & 31;
            int ktg = kt + ((kt >= 16) ? 96 : 0);
            float s, c; sincospif((float)(q*ktg) * (1.0f/64.0f), &s, &c);
            g_T2[i] = make_float2(c, s);
        }
    } else if (blk == 258) {
        for (int i = tid; i < 1024; i += 256) {
            int kt = i >> 5, q = i & 31;
            int ktg = kt + ((kt >= 16) ? 96 : 0);
            float s, c; sincospif((float)(q*ktg) * (1.0f/64.0f), &s, &c);
            g_T4[i] = make_float2(c, s);
        }
    } else {
        for (int i = tid; i < 1024; i += 256) {
            int kx = i >> 6, q = i & 63;
            float s, c; sincospif((float)(q*kx) * (1.0f/128.0f), &s, &c);
            g_T5cc[i] = make_float2(c, c);
            g_T5ss[i] = make_float2(s, s);
        }
    }
}

// ---------------- k1: x-DFT radix-4, FFMA2 over t-pairs -------------------
// grid 2048 = (bi, 16-t chunk); block 128: warp w = class, lane = (j kx, tp)
__global__ void __launch_bounds__(128) k1_xdft(const float* __restrict__ x) {
    __shared__ float2 E0[8*193], E2[8*193], DA[8*193], DB[8*193];  // [tp][q*3+p] = (t0,t1)
    int blk = blockIdx.x, tid = threadIdx.x;
    int bi = blk >> 3, tc = blk & 7;
    const float* src = x + ((size_t)bi*128 + tc*16) * 768;
    for (int idx = tid; idx < 3072; idx += 128) {
        int ts = idx / 192, r = idx - ts*192;
        const float* s = src + ts*768 + r;
        float x0 = s[0], x1 = s[192], x2 = s[384], x3 = s[576];
        float s02 = x0 + x2, s13 = x1 + x3;
        int tp = ts >> 1, h = ts & 1, e = (tp*193 + r)*2 + h;
        ((float*)E0)[e] = s02 + s13;
        ((float*)E2)[e] = s02 - s13;
        ((float*)DA)[e] = x0 - x2;
        ((float*)DB)[e] = x1 - x3;
    }
    __syncthreads();
    int w = tid >> 5, lane = tid & 31;
    int j = lane >> 3, tp = lane & 7;
    int kx = w + 4*j;
    const u64* cc = (const u64*)g_T1cc;
    const u64* ss = (const u64*)g_T1ss;
    int t0 = tc*16 + tp*2;
    if ((w & 1) == 0) {
        const u64* row = (const u64*)((w == 0 ? E0 : E2) + tp*193);
        u64 R[3] = {0,0,0}, I[3] = {0,0,0};
        #pragma unroll 8
        for (int q = 0; q < 64; q++) {
            u64 c = __ldg(cc + q*16 + kx), s = __ldg(ss + q*16 + kx);
            #pragma unroll
            for (int p = 0; p < 3; p++) {
                u64 v = row[q*3 + p];
                ffma2(R[p], v, c);
                ffma2(I[p], v, s);
            }
        }
        #pragma unroll
        for (int p = 0; p < 3; p++) {
            float2 r = u2f(R[p]), i = u2f(I[p]);
            float4 o = make_float4(r.x, -i.x, r.y, -i.y);
            *(float4*)(g_A + (size_t)((bi*16 + kx)*3 + p)*128 + t0) = o;
        }
    } else {
        const u64* ra = (const u64*)(DA + tp*193);
        const u64* rb = (const u64*)(DB + tp*193);
        u64 RA[3]={0,0,0}, RB[3]={0,0,0}, IA[3]={0,0,0}, IB[3]={0,0,0};
        #pragma unroll 8
        for (int q = 0; q < 64; q++) {
            u64 c = __ldg(cc + q*16 + kx), s = __ldg(ss + q*16 + kx);
            #pragma unroll
            for (int p = 0; p < 3; p++) {
                u64 va = ra[q*3 + p], vb = rb[q*3 + p];
                ffma2(RA[p], va, c);
                ffma2(IA[p], va, s);
                ffma2(RB[p], vb, s);
                ffma2(IB[p], vb, c);
            }
        }
        float sg = (w == 1) ? -1.f : 1.f;   // class1: b=-d13; class3: b=+d13
        #pragma unroll
        for (int p = 0; p < 3; p++) {
            float2 rA = u2f(RA[p]), rB = u2f(RB[p]), iA = u2f(IA[p]), iB = u2f(IB[p]);
            float4 o = make_float4(rA.x + sg*rB.x, sg*iB.x - iA.x,
                                   rA.y + sg*rB.y, sg*iB.y - iA.y);
            *(float4*)(g_A + (size_t)((bi*16 + kx)*3 + p)*128 + t0) = o;
        }
    }
}

// ---------------- k2: t-DFT (128 -> 32 modes) radix-4 + p-rfft ------------
// grid 4096 = (bi, kx); block 96 = (kt 32) x (p 3)
__global__ void k2_tdft() {
    __shared__ float2 As[384];
    __shared__ float2 Ys[384];          // [c][p][q<32]
    __shared__ float2 Xt[32][3];
    int blk = blockIdx.x, tid = threadIdx.x;
    int bi = blk >> 4, kx = blk & 15;
    const float2* src = g_A + (size_t)(bi*16 + kx)*384;
    for (int i = tid; i < 384; i += 96) As[i] = src[i];
    __syncthreads();
    {
        int p = tid / 32, q = tid & 31;
        float2 A0 = As[p*128 + q], A1 = As[p*128 + q + 32];
        float2 A2 = As[p*128 + q + 64], A3 = As[p*128 + q + 96];
        float Dx = A0.x - A2.x, Dy = A0.y - A2.y;
        float Ex = A1.x - A3.x, Ey = A1.y - A3.y;
        Ys[(0*3 + p)*32 + q] = make_float2(A0.x+A1.x+A2.x+A3.x, A0.y+A1.y+A2.y+A3.y);
        Ys[(1*3 + p)*32 + q] = make_float2(Dx + Ey, Dy - Ex);
        Ys[(2*3 + p)*32 + q] = make_float2(A0.x-A1.x+A2.x-A3.x, A0.y-A1.y+A2.y-A3.y);
        Ys[(3*3 + p)*32 + q] = make_float2(Dx - Ey, Dy + Ex);
    }
    __syncthreads();
    int kt = tid & 31, p = tid >> 5;
    const float2* Yp = Ys + ((kt & 3)*3 + p)*32;
    float re = 0.f, im = 0.f;
    #pragma unroll
    for (int q = 0; q < 32; q++) {
        float2 y = Yp[q];
        float2 cs = __ldg(&g_T2[q*32 + kt]);
        re += y.x*cs.x + y.y*cs.y;
        im += y.y*cs.x - y.x*cs.y;
    }
    Xt[kt][p] = make_float2(re, im);
    __syncthreads();
    if (tid < 64) {
        int kt2 = tid & 31, kz = tid >> 5;
        float2 a0 = Xt[kt2][0], a1 = Xt[kt2][1], a2 = Xt[kt2][2];
        float2 rr;
        if (kz == 0) rr = make_float2(a0.x + a1.x + a2.x, a0.y + a1.y + a2.y);
        else rr = make_float2(a0.x - 0.5f*(a1.x + a2.x) + S3*(a1.y - a2.y),
                              a0.y - 0.5f*(a1.y + a2.y) - S3*(a1.x - a2.x));
        g_X[(size_t)((kt2*16 + kx)*2 + kz)*256 + bi] = rr;
    }
}

// ---------------- k3: per-mode complex GEMM -------------------------------
__global__ void k3_mix() {
    __shared__ float2 Xs[256];
    __shared__ float2 Ws[1024];
    int mode = blockIdx.x, tid = threadIdx.x;
    Xs[tid] = g_X[(size_t)mode*256 + tid];
    const float4* wsrc = (const float4*)(g_W + (size_t)mode*1024);
    float4* wdst = (float4*)Ws;
    wdst[tid]       = wsrc[tid];
    wdst[tid + 256] = wsrc[tid + 256];
    __syncthreads();
    int b = tid >> 5, o = tid & 31;
    float re0=0, im0=0, re1=0, im1=0;
    #pragma unroll
    for (int i = 0; i < 32; i += 2) {
        float2 xv = Xs[b*32 + i];     float2 wv = Ws[i*32 + o];
        re0 += xv.x*wv.x - xv.y*wv.y; im0 += xv.x*wv.y + xv.y*wv.x;
        float2 xq = Xs[b*32 + i + 1]; float2 wq = Ws[(i+1)*32 + o];
        re1 += xq.x*wq.x - xq.y*wq.y; im1 += xq.x*wq.y + xq.y*wq.x;
    }
    int kz = mode & 1, kx = (mode >> 1) & 15, kt = mode >> 5;
    g_Y[(size_t)(((b*32 + o)*16 + kx)*32 + kt)*2 + kz] = make_float2(re0+re1, im0+im1);
}

// ---------------- k4: build U_p, expand kt -> t radix-4 -------------------
// grid 4096 = (bo, kx); block 96 = (q 32) x (p 3)
__global__ void k4_texp() {
    __shared__ float2 Ys[64];
    __shared__ float2 U[96];
    int blk = blockIdx.x, tid = threadIdx.x;
    int bo = blk >> 4, kx = blk & 15;
    if (tid < 64) Ys[tid] = g_Y[(size_t)(bo*16 + kx)*64 + tid];
    __syncthreads();
    {
        int kt = tid & 31, p = tid / 32;
        float2 y0 = Ys[kt*2], y1 = Ys[kt*2 + 1];
        float wx, wy;
        if (p == 0)      { wx = 2.f;  wy = 0.f; }
        else if (p == 1) { wx = -1.f; wy =  2.f*S3; }
        else             { wx = -1.f; wy = -2.f*S3; }
        const float SC = 1.f/98304.f;
        U[kt*3 + p] = make_float2(SC*(y0.x + wx*y1.x - wy*y1.y),
                                  SC*(y0.y + wx*y1.y + wy*y1.x));
    }
    __syncthreads();
    int q = tid & 31, p = tid >> 5;
    float s0x=0,s0y=0, s1x=0,s1y=0, s2x=0,s2y=0, s3x=0,s3y=0;
    #pragma unroll
    for (int kt = 0; kt < 32; kt++) {
        float2 u = U[kt*3 + p];
        float2 cs = __ldg(&g_T4[kt*32 + q]);
        float tr = u.x*cs.x - u.y*cs.y;
        float ti = u.x*cs.y + u.y*cs.x;
        switch (kt & 3) {
            case 0: s0x += tr; s0y += ti; break;
            case 1: s1x += tr; s1y += ti; break;
            case 2: s2x += tr; s2y += ti; break;
            default: s3x += tr; s3y += ti; break;
        }
    }
    size_t base = (size_t)bo*128 + q;
    size_t off = (size_t)kx*3 + p;
    g_V[(base      )*48 + off] = make_float2(s0x+s1x+s2x+s3x, s0y+s1y+s2y+s3y);
    g_V[(base + 32 )*48 + off] = make_float2(s0x-s1y-s2x+s3y, s0y+s1x-s2y-s3x);
    g_V[(base + 64 )*48 + off] = make_float2(s0x-s1x+s2x-s3x, s0y-s1y+s2y-s3y);
    g_V[(base + 96 )*48 + off] = make_float2(s0x+s1y-s2x-s3y, s0y-s1x-s2y+s3x);
}

// ---------------- k5: x-expand radix-4, FFMA2 over t-pairs ----------------
// grid 4096 = (bo, t-oct); block 256 = (t-pair 4) x (q 64); 4 x * 2 t * 3 p out
__global__ void __launch_bounds__(256, 2) k5_xexp(float* __restrict__ out) {
    __shared__ float2 Vx[4*49], Vy[4*49];   // [pair][kx*3+p] = (t0,t1)
    int blk = blockIdx.x, tid = threadIdx.x;
    int bo = blk >> 4, toct = blk & 15;
    for (int idx = tid; idx < 384; idx += 256) {          // FIX: full coverage
        int tl = idx / 48, i = idx % 48;
        float2 v = g_V[((size_t)bo*128 + toct*8 + tl)*48 + i];
        int pr = tl >> 1, h = tl & 1, e = (pr*49 + i)*2 + h;
        ((float*)Vx)[e] = v.x;
        ((float*)Vy)[e] = v.y;
    }
    __syncthreads();
    int pr = tid >> 6, q = tid & 63;
    const u64* vx = (const u64*)(Vx + pr*49);
    const u64* vy = (const u64*)(Vy + pr*49);
    const u64* cc = (const u64*)g_T5cc;
    const u64* ss = (const u64*)g_T5ss;
    u64 A0[3]={0,0,0}, B0[3]={0,0,0};
    u64 A1[3]={0,0,0}, B1[3]={0,0,0}, C1[3]={0,0,0}, D1[3]={0,0,0};
    u64 A2[3]={0,0,0}, B2[3]={0,0,0};
    u64 A3[3]={0,0,0}, B3[3]={0,0,0}, C3[3]={0,0,0}, D3[3]={0,0,0};
    #pragma unroll
    for (int kx = 0; kx < 16; kx++) {
        u64 c = __ldg(cc + kx*64 + q), s = __ldg(ss + kx*64 + q);
        #pragma unroll
        for (int p = 0; p < 3; p++) {
            u64 x = vx[kx*3 + p], y = vy[kx*3 + p];
            switch (kx & 3) {
                case 0: ffma2(A0[p], x, c); ffma2(B0[p], y, s); break;
                case 1: ffma2(A1[p], x, c); ffma2(B1[p], y, s);
                        ffma2(C1[p], x, s); ffma2(D1[p], y, c); break;
                case 2: ffma2(A2[p], x, c); ffma2(B2[p], y, s); break;
                default:ffma2(A3[p], x, c); ffma2(B3[p], y, s);
                        ffma2(C3[p], x, s); ffma2(D3[p], y, c); break;
            }
        }
    }
    int tbase = toct*8 + pr*2;
    float* r0 = out + ((size_t)bo*128 + tbase)*768;
    float* r1 = r0 + 768;
    #pragma unroll
    for (int p = 0; p < 3; p++) {
        float2 a0 = u2f(A0[p]), b0 = u2f(B0[p]);
        float2 a1 = u2f(A1[p]), b1 = u2f(B1[p]), c1 = u2f(C1[p]), d1 = u2f(D1[p]);
        float2 a2 = u2f(A2[p]), b2 = u2f(B2[p]);
        float2 a3 = u2f(A3[p]), b3 = u2f(B3[p]), c3 = u2f(C3[p]), d3 = u2f(D3[p]);
        #pragma unroll
        for (int h = 0; h < 2; h++) {
            float tr0 = h ? a0.y-b0.y : a0.x-b0.x;
            float tr1 = h ? a1.y-b1.y : a1.x-b1.x;
            float ti1 = h ? c1.y+d1.y : c1.x+d1.x;
            float tr2 = h ? a2.y-b2.y : a2.x-b2.x;
            float tr3 = h ? a3.y-b3.y : a3.x-b3.x;
            float ti3 = h ? c3.y+d3.y : c3.x+d3.x;
            float e = tr0 + tr2, f = tr0 - tr2;
            float g1 = tr1 + tr3, dti = ti3 - ti1;
            float* row = h ? r1 : r0;
            row[(q      )*3 + p] = e + g1;
            row[(q + 64 )*3 + p] = f + dti;
            row[(q + 128)*3 + p] = e - g1;
            row[(q + 192)*3 + p] = f - dti;
        }
    }
}

extern "C" void kernel_launch(void* const* d_in, const int* in_sizes, int n_in,
                              void* d_out, int out_size) {
    const float* x    = (const float*)d_in[0];
    const float* w1re = (const float*)d_in[1];
    const float* w1im = (const float*)d_in[2];
    const float* w2re = (const float*)d_in[3];
    const float* w2im = (const float*)d_in[4];
    float* out = (float*)d_out;

    k0_prep<<<260,   256>>>(w1re, w1im, w2re, w2im);
    k1_xdft<<<2048,  128>>>(x);
    k2_tdft<<<4096,   96>>>();
    k3_mix <<<1024,  256>>>();
    k4_texp<<<4096,   96>>>();
    k5_xexp<<<4096,  256>>>(out);
}

// round 8
// speedup vs baseline: 3.1610x; 1.0501x over previous
#include <cuda_runtime.h>

#define S3 0.86602540378443864676f   // sqrt(3)/2
typedef unsigned long long u64;

__device__ __forceinline__ void ffma2(u64 &d, u64 a, u64 b) {
    asm("fma.rn.f32x2 %0, %1, %2, %0;" : "+l"(d) : "l"(a), "l"(b));
}
__device__ __forceinline__ float2 u2f(u64 v) {
    float2 f; asm("mov.b64 {%0,%1}, %2;" : "=f"(f.x), "=f"(f.y) : "l"(v)); return f;
}

// ---------------- scratch ----------------
__device__ float2 g_X[1024*256];        // [mode][b*32+i]
__device__ float2 g_W[1024*1024];       // [mode][i*32+o]
__device__ float2 g_Y[8*32*16*32*2];    // [bo][kx][kt][kz]
// twiddle tables
__device__ float2 g_T1cc[64*16];        // [q][kx] (c,c)   th = 2pi q kx/256
__device__ float2 g_T1ss[64*16];        // [q][kx] (s,s)
__device__ float2 g_T2[32*32];          // [q][kt] (c,s)   ph = 2pi q ktg/128
__device__ float2 g_T4[32*32];          // [kt][q] (c,s)
__device__ float2 g_T5cc[16*64];        // [kx][q] (c,c)   th = 2pi q kx/256
__device__ float2 g_T5ss[16*64];        // [kx][q] (s,s)

// ---------------- k0: tiled weight transpose + tables ---------------------
__global__ void k0_prep(const float* __restrict__ w1re, const float* __restrict__ w1im,
                        const float* __restrict__ w2re, const float* __restrict__ w2im) {
    int blk = blockIdx.x, tid = threadIdx.x;
    if (blk < 256) {
        __shared__ float2 t1[64*33], t2[64*33];
        int io0 = (blk >> 3) * 32, e0 = (blk & 7) * 64;
        int el = tid & 63, iol = tid >> 6;
        int e = e0 + el;
        int ktw = e >> 5, kx = (e >> 1) & 15, kz = e & 1;
        int off = ktw*48 + kx*3 + kz;
        #pragma unroll
        for (int pass = 0; pass < 8; pass++) {
            int il = pass*4 + iol;
            int s = (io0 + il)*768 + off;
            t1[el*33 + il] = make_float2(w1re[s], w1im[s]);
            t2[el*33 + il] = make_float2(w2re[s], w2im[s]);
        }
        __syncthreads();
        int il2 = tid & 31;
        #pragma unroll
        for (int pass = 0; pass < 8; pass++) {
            int el2 = pass*8 + (tid >> 5);
            g_W[(size_t)(e0 + el2)*1024 + io0 + il2]       = t1[el2*33 + il2];
            g_W[(size_t)(e0 + el2 + 512)*1024 + io0 + il2] = t2[el2*33 + il2];
        }
    } else if (blk == 256) {
        for (int i = tid; i < 1024; i += 256) {
            int q = i >> 4, kx = i & 15;
            float s, c; sincospif((float)(q*kx) * (1.0f/128.0f), &s, &c);
            g_T1cc[i] = make_float2(c, c);
            g_T1ss[i] = make_float2(s, s);
        }
    } else if (blk == 257) {
        for (int i = tid; i < 1024; i += 256) {
            int q = i >> 5, kt = i & 31;
            int ktg = kt + ((kt >= 16) ? 96 : 0);
            float s, c; sincospif((float)(q*ktg) * (1.0f/64.0f), &s, &c);
            g_T2[i] = make_float2(c, s);
        }
    } else if (blk == 258) {
        for (int i = tid; i < 1024; i += 256) {
            int kt = i >> 5, q = i & 31;
            int ktg = kt + ((kt >= 16) ? 96 : 0);
            float s, c; sincospif((float)(q*ktg) * (1.0f/64.0f), &s, &c);
            g_T4[i] = make_float2(c, s);
        }
    } else {
        for (int i = tid; i < 1024; i += 256) {
            int kx = i >> 6, q = i & 63;
            float s, c; sincospif((float)(q*kx) * (1.0f/128.0f), &s, &c);
            g_T5cc[i] = make_float2(c, c);
            g_T5ss[i] = make_float2(s, s);
        }
    }
}

// ---------------- kA: fused x-DFT + t-DFT + p-rfft ------------------------
// grid 256 = bi; block 384 = 3 chunk-groups x 4 class-warps
// dyn smem: A_sh[6144] + ST[3*4*1544] = 24672 float2 = 197376 B
__global__ void __launch_bounds__(384) kA_fwd(const float* __restrict__ x) {
    extern __shared__ float2 smem[];
    float2* A_sh = smem;                 // [kx][p][t] 16*3*128
    float2* ST   = smem + 6144;          // 3 groups * 4 bufs * 1544
    int bi = blockIdx.x, tid = threadIdx.x;
    int g = tid >> 7, tidl = tid & 127;

    float2* E0 = ST + g*6176;
    float2* E2 = E0 + 1544;
    float2* DA = E0 + 3088;
    float2* DB = E0 + 4632;

    // ---- phase 1: x-DFT (radix-4, FFMA2 over t-pairs), 8 chunks of 16 t --
    for (int it = 0; it < 3; it++) {
        int chunk = it*3 + g;
        if (chunk < 8) {
            const float* src = x + ((size_t)bi*128 + chunk*16) * 768;
            for (int idx = tidl; idx < 3072; idx += 128) {
                int ts = idx / 192, r = idx - ts*192;
                const float* s = src + ts*768 + r;
                float x0 = s[0], x1 = s[192], x2 = s[384], x3 = s[576];
                float s02 = x0 + x2, s13 = x1 + x3;
                int tp = ts >> 1, h = ts & 1, e = (tp*193 + r)*2 + h;
                ((float*)E0)[e] = s02 + s13;
                ((float*)E2)[e] = s02 - s13;
                ((float*)DA)[e] = x0 - x2;
                ((float*)DB)[e] = x1 - x3;
            }
        }
        __syncthreads();
        if (chunk < 8) {
            int w = (tidl >> 5), lane = tidl & 31;
            int j = lane >> 3, tp = lane & 7;
            int kx = w + 4*j;
            const u64* cc = (const u64*)g_T1cc;
            const u64* ss = (const u64*)g_T1ss;
            int t0 = chunk*16 + tp*2;
            if ((w & 1) == 0) {
                const u64* row = (const u64*)((w == 0 ? E0 : E2) + tp*193);
                u64 R[3] = {0,0,0}, I[3] = {0,0,0};
                #pragma unroll 8
                for (int q = 0; q < 64; q++) {
                    u64 c = __ldg(cc + q*16 + kx), s = __ldg(ss + q*16 + kx);
                    #pragma unroll
                    for (int p = 0; p < 3; p++) {
                        u64 v = row[q*3 + p];
                        ffma2(R[p], v, c);
                        ffma2(I[p], v, s);
                    }
                }
                #pragma unroll
                for (int p = 0; p < 3; p++) {
                    float2 r = u2f(R[p]), i = u2f(I[p]);
                    float4 o = make_float4(r.x, -i.x, r.y, -i.y);
                    *(float4*)(A_sh + (kx*3 + p)*128 + t0) = o;
                }
            } else {
                const u64* ra = (const u64*)(DA + tp*193);
                const u64* rb = (const u64*)(DB + tp*193);
                u64 RA[3]={0,0,0}, RB[3]={0,0,0}, IA[3]={0,0,0}, IB[3]={0,0,0};
                #pragma unroll 8
                for (int q = 0; q < 64; q++) {
                    u64 c = __ldg(cc + q*16 + kx), s = __ldg(ss + q*16 + kx);
                    #pragma unroll
                    for (int p = 0; p < 3; p++) {
                        u64 va = ra[q*3 + p], vb = rb[q*3 + p];
                        ffma2(RA[p], va, c);
                        ffma2(IA[p], va, s);
                        ffma2(RB[p], vb, s);
                        ffma2(IB[p], vb, c);
                    }
                }
                float sg = (w == 1) ? -1.f : 1.f;   // class1: b=-d13; class3: b=+d13
                #pragma unroll
                for (int p = 0; p < 3; p++) {
                    float2 rA = u2f(RA[p]), rB = u2f(RB[p]), iA = u2f(IA[p]), iB = u2f(IB[p]);
                    float4 o = make_float4(rA.x + sg*rB.x, sg*iB.x - iA.x,
                                           rA.y + sg*rB.y, sg*iB.y - iA.y);
                    *(float4*)(A_sh + (kx*3 + p)*128 + t0) = o;
                }
            }
        }
        __syncthreads();
    }

    // ---- phase 2: t-DFT radix-4 + p-rfft, all 16 kx in-block ------------
    float2* Ys = ST;              // [kx][(c*3+p)*32+q]  16*384
    float2* Xt = ST + 6144;       // [(kx*32+kt)*3+p]    1536
    for (int idx = tid; idx < 1536; idx += 384) {         // class build
        int kx = idx / 96, r = idx - kx*96;
        int p = r >> 5, q = r & 31;
        const float2* Ap = A_sh + kx*384 + p*128;
        float2 A0 = Ap[q], A1 = Ap[q + 32], A2 = Ap[q + 64], A3 = Ap[q + 96];
        float Dx = A0.x - A2.x, Dy = A0.y - A2.y;
        float Ex = A1.x - A3.x, Ey = A1.y - A3.y;
        float2* Yk = Ys + kx*384;
        Yk[(0*3 + p)*32 + q] = make_float2(A0.x+A1.x+A2.x+A3.x, A0.y+A1.y+A2.y+A3.y);
        Yk[(1*3 + p)*32 + q] = make_float2(Dx + Ey, Dy - Ex);
        Yk[(2*3 + p)*32 + q] = make_float2(A0.x-A1.x+A2.x-A3.x, A0.y-A1.y+A2.y-A3.y);
        Yk[(3*3 + p)*32 + q] = make_float2(Dx - Ey, Dy + Ex);
    }
    __syncthreads();
    for (int idx = tid; idx < 1536; idx += 384) {         // mode dot products
        int kx = idx / 96, r = idx - kx*96;
        int kt = r & 31, p = r >> 5;
        const float2* Yp = Ys + kx*384 + ((kt & 3)*3 + p)*32;
        float re = 0.f, im = 0.f;
        #pragma unroll
        for (int q = 0; q < 32; q++) {
            float2 y = Yp[q];
            float2 cs = __ldg(&g_T2[q*32 + kt]);
            re += y.x*cs.x + y.y*cs.y;
            im += y.y*cs.x - y.x*cs.y;
        }
        Xt[(kx*32 + kt)*3 + p] = make_float2(re, im);
    }
    __syncthreads();
    for (int idx = tid; idx < 1024; idx += 384) {         // p-rfft + store
        int kx = idx >> 6, r = idx & 63;
        int kt = r & 31, kz = r >> 5;
        const float2* Xp = Xt + (kx*32 + kt)*3;
        float2 a0 = Xp[0], a1 = Xp[1], a2 = Xp[2];
        float2 rr;
        if (kz == 0) rr = make_float2(a0.x + a1.x + a2.x, a0.y + a1.y + a2.y);
        else rr = make_float2(a0.x - 0.5f*(a1.x + a2.x) + S3*(a1.y - a2.y),
                              a0.y - 0.5f*(a1.y + a2.y) - S3*(a1.x - a2.x));
        g_X[(size_t)((kt*16 + kx)*2 + kz)*256 + bi] = rr;
    }
}

// ---------------- k3: per-mode complex GEMM -------------------------------
__global__ void k3_mix() {
    __shared__ float2 Xs[256];
    __shared__ float2 Ws[1024];
    int mode = blockIdx.x, tid = threadIdx.x;
    Xs[tid] = g_X[(size_t)mode*256 + tid];
    const float4* wsrc = (const float4*)(g_W + (size_t)mode*1024);
    float4* wdst = (float4*)Ws;
    wdst[tid]       = wsrc[tid];
    wdst[tid + 256] = wsrc[tid + 256];
    __syncthreads();
    int b = tid >> 5, o = tid & 31;
    float re0=0, im0=0, re1=0, im1=0;
    #pragma unroll
    for (int i = 0; i < 32; i += 2) {
        float2 xv = Xs[b*32 + i];     float2 wv = Ws[i*32 + o];
        re0 += xv.x*wv.x - xv.y*wv.y; im0 += xv.x*wv.y + xv.y*wv.x;
        float2 xq = Xs[b*32 + i + 1]; float2 wq = Ws[(i+1)*32 + o];
        re1 += xq.x*wq.x - xq.y*wq.y; im1 += xq.x*wq.y + xq.y*wq.x;
    }
    int kz = mode & 1, kx = (mode >> 1) & 15, kt = mode >> 5;
    g_Y[(size_t)(((b*32 + o)*16 + kx)*32 + kt)*2 + kz] = make_float2(re0+re1, im0+im1);
}

// ---------------- kB: fused U-build + t-expand + x-expand -----------------
// grid 256 = bo; block 512
// dyn smem: Y 1024 + U 1536 + Vx 3136 + Vy 3136 = 8832 float2 = 70656 B
__global__ void __launch_bounds__(512) kB_inv(float* __restrict__ out) {
    extern __shared__ float2 smem[];
    float2* Y_sh = smem;            // [kx*64 + kt*2 + kz]
    float2* U_sh = smem + 1024;     // [kx*96 + kt*3 + p]
    float2* Vx   = smem + 2560;     // [pr*49 + kx*3 + p] = (t0,t1) re
    float2* Vy   = smem + 5696;     //                       (t0,t1) im
    int bo = blockIdx.x, tid = threadIdx.x;

    // B1: load Y slice (coalesced float4)
    ((float4*)Y_sh)[tid] = ((const float4*)(g_Y + (size_t)bo*1024))[tid];
    __syncthreads();

    // B2: build U
    for (int idx = tid; idx < 1536; idx += 512) {
        int kx = idx / 96, r = idx - kx*96;
        int kt = r & 31, p = r >> 5;
        float2 y0 = Y_sh[kx*64 + kt*2], y1 = Y_sh[kx*64 + kt*2 + 1];
        float wx, wy;                          // 2 * e^{2 pi i p / 3}
        if (p == 0)      { wx = 2.f;  wy = 0.f; }
        else if (p == 1) { wx = -1.f; wy =  2.f*S3; }
        else             { wx = -1.f; wy = -2.f*S3; }
        const float SC = 1.f/98304.f;          // 1/(128*256*3)
        U_sh[kx*96 + kt*3 + p] = make_float2(SC*(y0.x + wx*y1.x - wy*y1.y),
                                             SC*(y0.y + wx*y1.y + wy*y1.x));
    }
    __syncthreads();

    // B3: t-expand radix-4 -> Vx/Vy (SoA t-pairs)
    for (int idx = tid; idx < 1536; idx += 512) {
        int kx = idx / 96, r = idx - kx*96;
        int q = r & 31, p = r >> 5;
        float s0x=0,s0y=0, s1x=0,s1y=0, s2x=0,s2y=0, s3x=0,s3y=0;
        #pragma unroll
        for (int kt = 0; kt < 32; kt++) {
            float2 u = U_sh[kx*96 + kt*3 + p];
            float2 cs = __ldg(&g_T4[kt*32 + q]);
            float tr = u.x*cs.x - u.y*cs.y;
            float ti = u.x*cs.y + u.y*cs.x;
            switch (kt & 3) {
                case 0: s0x += tr; s0y += ti; break;
                case 1: s1x += tr; s1y += ti; break;
                case 2: s2x += tr; s2y += ti; break;
                default: s3x += tr; s3y += ti; break;
            }
        }
        float vr[4], vi[4];
        vr[0] = s0x+s1x+s2x+s3x; vi[0] = s0y+s1y+s2y+s3y;
        vr[1] = s0x-s1y-s2x+s3y; vi[1] = s0y+s1x-s2y-s3x;
        vr[2] = s0x-s1x+s2x-s3x; vi[2] = s0y-s1y+s2y-s3y;
        vr[3] = s0x+s1y-s2x-s3y; vi[3] = s0y-s1x-s2y+s3x;
        int h = q & 1;
        #pragma unroll
        for (int m = 0; m < 4; m++) {
            int pr = (q >> 1) + 16*m;
            int e = (pr*49 + kx*3 + p)*2 + h;
            ((float*)Vx)[e] = vr[m];
            ((float*)Vy)[e] = vi[m];
        }
    }
    __syncthreads();

    // B4: x-expand radix-4, FFMA2 over t-pairs, take Re, store
    const u64* cc = (const u64*)g_T5cc;
    const u64* ss = (const u64*)g_T5ss;
    for (int idx = tid; idx < 4096; idx += 512) {
        int pr = idx >> 6, q = idx & 63;
        const u64* vx = (const u64*)(Vx + pr*49);
        const u64* vy = (const u64*)(Vy + pr*49);
        u64 A0[3]={0,0,0}, B0[3]={0,0,0};
        u64 A1[3]={0,0,0}, B1[3]={0,0,0}, C1[3]={0,0,0}, D1[3]={0,0,0};
        u64 A2[3]={0,0,0}, B2[3]={0,0,0};
        u64 A3[3]={0,0,0}, B3[3]={0,0,0}, C3[3]={0,0,0}, D3[3]={0,0,0};
        #pragma unroll
        for (int kx = 0; kx < 16; kx++) {
            u64 c = __ldg(cc + kx*64 + q), s = __ldg(ss + kx*64 + q);
            #pragma unroll
            for (int p = 0; p < 3; p++) {
                u64 xx = vx[kx*3 + p], yy = vy[kx*3 + p];
                switch (kx & 3) {
                    case 0: ffma2(A0[p], xx, c); ffma2(B0[p], yy, s); break;
                    case 1: ffma2(A1[p], xx, c); ffma2(B1[p], yy, s);
                            ffma2(C1[p], xx, s); ffma2(D1[p], yy, c); break;
                    case 2: ffma2(A2[p], xx, c); ffma2(B2[p], yy, s); break;
                    default:ffma2(A3[p], xx, c); ffma2(B3[p], yy, s);
                            ffma2(C3[p], xx, s); ffma2(D3[p], yy, c); break;
                }
            }
        }
        float* r0 = out + ((size_t)bo*128 + pr*2)*768;
        float* r1 = r0 + 768;
        #pragma unroll
        for (int p = 0; p < 3; p++) {
            float2 a0 = u2f(A0[p]), b0 = u2f(B0[p]);
            float2 a1 = u2f(A1[p]), b1 = u2f(B1[p]), c1 = u2f(C1[p]), d1 = u2f(D1[p]);
            float2 a2 = u2f(A2[p]), b2 = u2f(B2[p]);
            float2 a3 = u2f(A3[p]), b3 = u2f(B3[p]), c3 = u2f(C3[p]), d3 = u2f(D3[p]);
            #pragma unroll
            for (int h = 0; h < 2; h++) {
                float tr0 = h ? a0.y-b0.y : a0.x-b0.x;
                float tr1 = h ? a1.y-b1.y : a1.x-b1.x;
                float ti1 = h ? c1.y+d1.y : c1.x+d1.x;
                float tr2 = h ? a2.y-b2.y : a2.x-b2.x;
                float tr3 = h ? a3.y-b3.y : a3.x-b3.x;
                float ti3 = h ? c3.y+d3.y : c3.x+d3.x;
                float e = tr0 + tr2, f = tr0 - tr2;
                float g1 = tr1 + tr3, dti = ti3 - ti1;
                float* row = h ? r1 : r0;
                row[(q      )*3 + p] = e + g1;
                row[(q + 64 )*3 + p] = f + dti;
                row[(q + 128)*3 + p] = e - g1;
                row[(q + 192)*3 + p] = f - dti;
            }
        }
    }
}

extern "C" void kernel_launch(void* const* d_in, const int* in_sizes, int n_in,
                              void* d_out, int out_size) {
    const float* x    = (const float*)d_in[0];
    const float* w1re = (const float*)d_in[1];
    const float* w1im = (const float*)d_in[2];
    const float* w2re = (const float*)d_in[3];
    const float* w2im = (const float*)d_in[4];
    float* out = (float*)d_out;

    static int attr_done = 0;
    if (!attr_done) {
        cudaFuncSetAttribute(kA_fwd, cudaFuncAttributeMaxDynamicSharedMemorySize, 197376);
        cudaFuncSetAttribute(kB_inv, cudaFuncAttributeMaxDynamicSharedMemorySize, 70656);
        attr_done = 1;
    }

    k0_prep<<<260, 256>>>(w1re, w1im, w2re, w2im);
    kA_fwd<<<256, 384, 197376>>>(x);
    k3_mix<<<1024, 256>>>();
    kB_inv<<<256, 512, 70656>>>(out);
}

// round 9
// speedup vs baseline: 3.2905x; 1.0410x over previous
#include <cuda_runtime.h>

#define S3 0.86602540378443864676f   // sqrt(3)/2
typedef unsigned long long u64;

__device__ __forceinline__ void ffma2(u64 &d, u64 a, u64 b) {
    asm("fma.rn.f32x2 %0, %1, %2, %0;" : "+l"(d) : "l"(a), "l"(b));
}
__device__ __forceinline__ float2 u2f(u64 v) {
    float2 f; asm("mov.b64 {%0,%1}, %2;" : "=f"(f.x), "=f"(f.y) : "l"(v)); return f;
}

// ---------------- scratch ----------------
__device__ float2 g_X[1024*256];        // [mode][b*32+i]
__device__ float2 g_W[1024*1024];       // [mode][i*32+o]
__device__ float2 g_Y[8*32*16*32*2];    // [bo][kx][kt][kz]
// twiddle tables
__device__ float4 g_T1q[64*16];         // [q][kx] (c,c,s,s)  th = 2pi q kx/256
__device__ float2 g_T2[32*32];          // [q][kt] (c,s)      ph = 2pi q ktg/128
__device__ float2 g_T4[32*32];          // [kt][q] (c,s)
__device__ float4 g_T5q[16*64];         // [kx][q] (c,c,s,s)  th = 2pi q kx/256

// ---------------- k0: tiled weight transpose + tables ---------------------
__global__ void k0_prep(const float* __restrict__ w1re, const float* __restrict__ w1im,
                        const float* __restrict__ w2re, const float* __restrict__ w2im) {
    int blk = blockIdx.x, tid = threadIdx.x;
    if (blk < 256) {
        __shared__ float2 t1[64*33], t2[64*33];
        int io0 = (blk >> 3) * 32, e0 = (blk & 7) * 64;
        int el = tid & 63, iol = tid >> 6;
        int e = e0 + el;
        int ktw = e >> 5, kx = (e >> 1) & 15, kz = e & 1;
        int off = ktw*48 + kx*3 + kz;
        #pragma unroll
        for (int pass = 0; pass < 8; pass++) {
            int il = pass*4 + iol;
            int s = (io0 + il)*768 + off;
            t1[el*33 + il] = make_float2(w1re[s], w1im[s]);
            t2[el*33 + il] = make_float2(w2re[s], w2im[s]);
        }
        __syncthreads();
        int il2 = tid & 31;
        #pragma unroll
        for (int pass = 0; pass < 8; pass++) {
            int el2 = pass*8 + (tid >> 5);
            g_W[(size_t)(e0 + el2)*1024 + io0 + il2]       = t1[el2*33 + il2];
            g_W[(size_t)(e0 + el2 + 512)*1024 + io0 + il2] = t2[el2*33 + il2];
        }
    } else if (blk == 256) {
        for (int i = tid; i < 1024; i += 256) {
            int q = i >> 4, kx = i & 15;
            float s, c; sincospif((float)(q*kx) * (1.0f/128.0f), &s, &c);
            g_T1q[i] = make_float4(c, c, s, s);
        }
    } else if (blk == 257) {
        for (int i = tid; i < 1024; i += 256) {
            int q = i >> 5, kt = i & 31;
            int ktg = kt + ((kt >= 16) ? 96 : 0);
            float s, c; sincospif((float)(q*ktg) * (1.0f/64.0f), &s, &c);
            g_T2[i] = make_float2(c, s);
        }
    } else if (blk == 258) {
        for (int i = tid; i < 1024; i += 256) {
            int kt = i >> 5, q = i & 31;
            int ktg = kt + ((kt >= 16) ? 96 : 0);
            float s, c; sincospif((float)(q*ktg) * (1.0f/64.0f), &s, &c);
            g_T4[i] = make_float2(c, s);
        }
    } else {
        for (int i = tid; i < 1024; i += 256) {
            int kx = i >> 6, q = i & 63;
            float s, c; sincospif((float)(q*kx) * (1.0f/128.0f), &s, &c);
            g_T5q[i] = make_float4(c, c, s, s);
        }
    }
}

// ---------------- kA: fused x-DFT + t-DFT + p-rfft ------------------------
// grid 256 = bi; block 384 = 12 warps = (class 4) x (p 3); lane = (j4, tp8)
// dyn smem: A_sh 6144 f2 + ST 6176 f2 = 12320 f2 = 98560 B -> 2 blocks/SM
__global__ void __launch_bounds__(384, 2) kA_fwd(const float* __restrict__ x) {
    extern __shared__ float2 smem[];
    float2* A_sh = smem;                 // [kx][p][t] 16*3*128
    float2* ST   = smem + 6144;          // staging (phase1) / Ys (phase2)
    int bi = blockIdx.x, tid = threadIdx.x;

    float2* E0 = ST;
    float2* E2 = ST + 1544;
    float2* DA = ST + 3088;
    float2* DB = ST + 4632;

    int w = tid >> 5, lane = tid & 31;
    int cls = w & 3, p = w >> 2;
    int j = lane >> 3, tp = lane & 7;
    int kx = cls + 4*j;
    const ulonglong2* T1 = (const ulonglong2*)g_T1q;

    // ---- phase 1: x-DFT radix-4, one 16-t chunk at a time ---------------
    for (int chunk = 0; chunk < 8; chunk++) {
        const float* src = x + ((size_t)bi*128 + chunk*16) * 768;
        for (int idx = tid; idx < 3072; idx += 384) {
            int ts = idx / 192, r = idx - ts*192;
            const float* s = src + ts*768 + r;
            float x0 = s[0], x1 = s[192], x2 = s[384], x3 = s[576];
            float s02 = x0 + x2, s13 = x1 + x3;
            int tpp = ts >> 1, h = ts & 1, e = (tpp*193 + r)*2 + h;
            ((float*)E0)[e] = s02 + s13;
            ((float*)E2)[e] = s02 - s13;
            ((float*)DA)[e] = x0 - x2;
            ((float*)DB)[e] = x1 - x3;
        }
        __syncthreads();
        int t0 = chunk*16 + tp*2;
        if ((cls & 1) == 0) {
            const u64* row = (const u64*)((cls == 0 ? E0 : E2) + tp*193);
            u64 R = 0, I = 0;
            #pragma unroll 16
            for (int q = 0; q < 64; q++) {
                ulonglong2 T = __ldg(T1 + q*16 + kx);
                u64 v = row[q*3 + p];
                ffma2(R, v, T.x);
                ffma2(I, v, T.y);
            }
            float2 r = u2f(R), i = u2f(I);
            *(float4*)(A_sh + (kx*3 + p)*128 + t0) = make_float4(r.x, -i.x, r.y, -i.y);
        } else {
            const u64* ra = (const u64*)(DA + tp*193);
            const u64* rb = (const u64*)(DB + tp*193);
            u64 RA=0, IA=0, RB=0, IB=0;
            #pragma unroll 16
            for (int q = 0; q < 64; q++) {
                ulonglong2 T = __ldg(T1 + q*16 + kx);
                u64 va = ra[q*3 + p], vb = rb[q*3 + p];
                ffma2(RA, va, T.x);
                ffma2(IA, va, T.y);
                ffma2(RB, vb, T.y);
                ffma2(IB, vb, T.x);
            }
            float sg = (cls == 1) ? -1.f : 1.f;   // class1: b=-d13; class3: b=+d13
            float2 rA = u2f(RA), rB = u2f(RB), iA = u2f(IA), iB = u2f(IB);
            *(float4*)(A_sh + (kx*3 + p)*128 + t0) =
                make_float4(rA.x + sg*rB.x, sg*iB.x - iA.x,
                            rA.y + sg*rB.y, sg*iB.y - iA.y);
        }
        __syncthreads();
    }

    // ---- phase 2: t-DFT radix-4 + p-rfft --------------------------------
    float2* Ys = ST;              // [kx][(c*3+p)*32+q]  16*384 = 6144
    float2* Xt = A_sh;            // aliases dead A_sh    1536
    for (int idx = tid; idx < 1536; idx += 384) {         // class build
        int kxx = idx / 96, r = idx - kxx*96;
        int pp = r >> 5, q = r & 31;
        const float2* Ap = A_sh + kxx*384 + pp*128;
        float2 A0 = Ap[q], A1 = Ap[q + 32], A2 = Ap[q + 64], A3 = Ap[q + 96];
        float Dx = A0.x - A2.x, Dy = A0.y - A2.y;
        float Ex = A1.x - A3.x, Ey = A1.y - A3.y;
        float2* Yk = Ys + kxx*384;
        Yk[(0*3 + pp)*32 + q] = make_float2(A0.x+A1.x+A2.x+A3.x, A0.y+A1.y+A2.y+A3.y);
        Yk[(1*3 + pp)*32 + q] = make_float2(Dx + Ey, Dy - Ex);
        Yk[(2*3 + pp)*32 + q] = make_float2(A0.x-A1.x+A2.x-A3.x, A0.y-A1.y+A2.y-A3.y);
        Yk[(3*3 + pp)*32 + q] = make_float2(Dx - Ey, Dy + Ex);
    }
    __syncthreads();
    for (int idx = tid; idx < 1536; idx += 384) {         // mode dot products
        int kxx = idx / 96, r = idx - kxx*96;
        int kt = r & 31, pp = r >> 5;
        const float2* Yp = Ys + kxx*384 + ((kt & 3)*3 + pp)*32;
        float re = 0.f, im = 0.f;
        #pragma unroll
        for (int q = 0; q < 32; q++) {
            float2 y = Yp[q];
            float2 cs = __ldg(&g_T2[q*32 + kt]);
            re += y.x*cs.x + y.y*cs.y;
            im += y.y*cs.x - y.x*cs.y;
        }
        Xt[(kxx*32 + kt)*3 + pp] = make_float2(re, im);
    }
    __syncthreads();
    for (int idx = tid; idx < 1024; idx += 384) {         // p-rfft + store
        int kxx = idx >> 6, r = idx & 63;
        int kt = r & 31, kz = r >> 5;
        const float2* Xp = Xt + (kxx*32 + kt)*3;
        float2 a0 = Xp[0], a1 = Xp[1], a2 = Xp[2];
        float2 rr;
        if (kz == 0) rr = make_float2(a0.x + a1.x + a2.x, a0.y + a1.y + a2.y);
        else rr = make_float2(a0.x - 0.5f*(a1.x + a2.x) + S3*(a1.y - a2.y),
                              a0.y - 0.5f*(a1.y + a2.y) - S3*(a1.x - a2.x));
        g_X[(size_t)((kt*16 + kxx)*2 + kz)*256 + bi] = rr;
    }
}

// ---------------- k3: per-mode complex GEMM -------------------------------
__global__ void k3_mix() {
    __shared__ float2 Xs[256];
    __shared__ float2 Ws[1024];
    int mode = blockIdx.x, tid = threadIdx.x;
    Xs[tid] = g_X[(size_t)mode*256 + tid];
    const float4* wsrc = (const float4*)(g_W + (size_t)mode*1024);
    float4* wdst = (float4*)Ws;
    wdst[tid]       = wsrc[tid];
    wdst[tid + 256] = wsrc[tid + 256];
    __syncthreads();
    int b = tid >> 5, o = tid & 31;
    float re0=0, im0=0, re1=0, im1=0;
    #pragma unroll
    for (int i = 0; i < 32; i += 2) {
        float2 xv = Xs[b*32 + i];     float2 wv = Ws[i*32 + o];
        re0 += xv.x*wv.x - xv.y*wv.y; im0 += xv.x*wv.y + xv.y*wv.x;
        float2 xq = Xs[b*32 + i + 1]; float2 wq = Ws[(i+1)*32 + o];
        re1 += xq.x*wq.x - xq.y*wq.y; im1 += xq.x*wq.y + xq.y*wq.x;
    }
    int kz = mode & 1, kx = (mode >> 1) & 15, kt = mode >> 5;
    g_Y[(size_t)(((b*32 + o)*16 + kx)*32 + kt)*2 + kz] = make_float2(re0+re1, im0+im1);
}

// ---------------- kB: fused U-build + t-expand + x-expand -----------------
// grid 256 = bo; block 384, 2 blocks/SM
// dyn smem: Y 1024 f2 + U 1536 f2 + Vq 64*49 u64x2 = 20480 + 50176 = 70656 B
__global__ void __launch_bounds__(384, 2) kB_inv(float* __restrict__ out) {
    extern __shared__ float2 smem[];
    float2* Y_sh = smem;                          // [kx*64 + kt*2 + kz]
    float2* U_sh = smem + 1024;                   // [kx*96 + kt*3 + p]
    ulonglong2* Vq = (ulonglong2*)(smem + 2560);  // [pr*49 + kx*3 + p] = (vx01, vy01)
    int bo = blockIdx.x, tid = threadIdx.x;

    // B1: load Y slice
    for (int idx = tid; idx < 512; idx += 384)
        ((float4*)Y_sh)[idx] = ((const float4*)(g_Y + (size_t)bo*1024))[idx];
    __syncthreads();

    // B2: build U
    for (int idx = tid; idx < 1536; idx += 384) {
        int kx = idx / 96, r = idx - kx*96;
        int kt = r & 31, p = r >> 5;
        float2 y0 = Y_sh[kx*64 + kt*2], y1 = Y_sh[kx*64 + kt*2 + 1];
        float wx, wy;                          // 2 * e^{2 pi i p / 3}
        if (p == 0)      { wx = 2.f;  wy = 0.f; }
        else if (p == 1) { wx = -1.f; wy =  2.f*S3; }
        else             { wx = -1.f; wy = -2.f*S3; }
        const float SC = 1.f/98304.f;          // 1/(128*256*3)
        U_sh[kx*96 + kt*3 + p] = make_float2(SC*(y0.x + wx*y1.x - wy*y1.y),
                                             SC*(y0.y + wx*y1.y + wy*y1.x));
    }
    __syncthreads();

    // B3: t-expand radix-4 -> Vq (SoA t-pairs, interleaved 16B entries)
    for (int idx = tid; idx < 1536; idx += 384) {
        int kx = idx / 96, r = idx - kx*96;
        int q = r & 31, p = r >> 5;
        float s0x=0,s0y=0, s1x=0,s1y=0, s2x=0,s2y=0, s3x=0,s3y=0;
        #pragma unroll
        for (int kt = 0; kt < 32; kt++) {
            float2 u = U_sh[kx*96 + kt*3 + p];
            float2 cs = __ldg(&g_T4[kt*32 + q]);
            float tr = u.x*cs.x - u.y*cs.y;
            float ti = u.x*cs.y + u.y*cs.x;
            switch (kt & 3) {
                case 0: s0x += tr; s0y += ti; break;
                case 1: s1x += tr; s1y += ti; break;
                case 2: s2x += tr; s2y += ti; break;
                default: s3x += tr; s3y += ti; break;
            }
        }
        float vr[4], vi[4];
        vr[0] = s0x+s1x+s2x+s3x; vi[0] = s0y+s1y+s2y+s3y;
        vr[1] = s0x-s1y-s2x+s3y; vi[1] = s0y+s1x-s2y-s3x;
        vr[2] = s0x-s1x+s2x-s3x; vi[2] = s0y-s1y+s2y-s3y;
        vr[3] = s0x+s1y-s2x-s3y; vi[3] = s0y-s1x-s2y+s3x;
        int h = q & 1;
        float* base = (float*)Vq;
        #pragma unroll
        for (int m = 0; m < 4; m++) {
            int pr = (q >> 1) + 16*m;
            int e4 = (pr*49 + kx*3 + p)*4;
            base[e4 + h]     = vr[m];
            base[e4 + 2 + h] = vi[m];
        }
    }
    __syncthreads();

    // B4: x-expand radix-4, FFMA2 over t-pairs, p-split, take Re, store
    const ulonglong2* T5 = (const ulonglong2*)g_T5q;
    for (int idx = tid; idx < 12288; idx += 384) {
        int pr = idx / 192, rem = idx - pr*192;
        int q = rem / 3, p = rem - q*3;
        const ulonglong2* vrow = Vq + pr*49 + p;
        u64 A0=0,B0=0, A1=0,B1=0,C1=0,D1=0, A2=0,B2=0, A3=0,B3=0,C3=0,D3=0;
        #pragma unroll
        for (int kx = 0; kx < 16; kx++) {
            ulonglong2 T = __ldg(T5 + kx*64 + q);
            ulonglong2 v = vrow[kx*3];
            switch (kx & 3) {
                case 0: ffma2(A0, v.x, T.x); ffma2(B0, v.y, T.y); break;
                case 1: ffma2(A1, v.x, T.x); ffma2(B1, v.y, T.y);
                        ffma2(C1, v.x, T.y); ffma2(D1, v.y, T.x); break;
                case 2: ffma2(A2, v.x, T.x); ffma2(B2, v.y, T.y); break;
                default:ffma2(A3, v.x, T.x); ffma2(B3, v.y, T.y);
                        ffma2(C3, v.x, T.y); ffma2(D3, v.y, T.x); break;
            }
        }
        float* r0 = out + ((size_t)bo*128 + pr*2)*768;
        float* r1 = r0 + 768;
        float2 a0 = u2f(A0), b0 = u2f(B0);
        float2 a1 = u2f(A1), b1 = u2f(B1), c1 = u2f(C1), d1 = u2f(D1);
        float2 a2 = u2f(A2), b2 = u2f(B2);
        float2 a3 = u2f(A3), b3 = u2f(B3), c3 = u2f(C3), d3 = u2f(D3);
        #pragma unroll
        for (int h = 0; h < 2; h++) {
            float tr0 = h ? a0.y-b0.y : a0.x-b0.x;
            float tr1 = h ? a1.y-b1.y : a1.x-b1.x;
            float ti1 = h ? c1.y+d1.y : c1.x+d1.x;
            float tr2 = h ? a2.y-b2.y : a2.x-b2.x;
            float tr3 = h ? a3.y-b3.y : a3.x-b3.x;
            float ti3 = h ? c3.y+d3.y : c3.x+d3.x;
            float e = tr0 + tr2, f = tr0 - tr2;
            float g1 = tr1 + tr3, dti = ti3 - ti1;
            float* row = h ? r1 : r0;
            row[(q      )*3 + p] = e + g1;
            row[(q + 64 )*3 + p] = f + dti;
            row[(q + 128)*3 + p] = e - g1;
            row[(q + 192)*3 + p] = f - dti;
        }
    }
}

extern "C" void kernel_launch(void* const* d_in, const int* in_sizes, int n_in,
                              void* d_out, int out_size) {
    const float* x    = (const float*)d_in[0];
    const float* w1re = (const float*)d_in[1];
    const float* w1im = (const float*)d_in[2];
    const float* w2re = (const float*)d_in[3];
    const float* w2im = (const float*)d_in[4];
    float* out = (float*)d_out;

    static int attr_done = 0;
    if (!attr_done) {
        cudaFuncSetAttribute(kA_fwd, cudaFuncAttributeMaxDynamicSharedMemorySize, 98560);
        cudaFuncSetAttribute(kB_inv, cudaFuncAttributeMaxDynamicSharedMemorySize, 70656);
        attr_done = 1;
    }

    k0_prep<<<260, 256>>>(w1re, w1im, w2re, w2im);
    kA_fwd<<<256, 384, 98560>>>(x);
    k3_mix<<<1024, 256>>>();
    kB_inv<<<256, 384, 70656>>>(out);
}

// round 10
// speedup vs baseline: 3.3035x; 1.0040x over previous
#include <cuda_runtime.h>

#define S3 0.86602540378443864676f   // sqrt(3)/2
typedef unsigned long long u64;

__device__ __forceinline__ void ffma2(u64 &d, u64 a, u64 b) {
    asm("fma.rn.f32x2 %0, %1, %2, %0;" : "+l"(d) : "l"(a), "l"(b));
}
__device__ __forceinline__ float2 u2f(u64 v) {
    float2 f; asm("mov.b64 {%0,%1}, %2;" : "=f"(f.x), "=f"(f.y) : "l"(v)); return f;
}
__device__ __forceinline__ u64 pack2(float lo, float hi) {
    u64 r; asm("mov.b64 %0, {%1,%2};" : "=l"(r) : "f"(lo), "f"(hi)); return r;
}

// ---------------- scratch ----------------
__device__ float2 g_X[1024*256];        // [mode][b*32+i]
__device__ float2 g_W[1024*1024];       // [mode][i*32+o]
__device__ float2 g_Y[8*32*16*32*2];    // [bo][kx][kt][kz]
// twiddle tables
__device__ float4 g_T1q[64*16];         // [q][kx] (c,c,s,s)  th = 2pi q kx/256
__device__ float2 g_T2[32*32];          // [q][kt] (c,s)      ph = 2pi q ktg/128
__device__ float2 g_T4[32*32];          // [kt][q] (c,s)
__device__ float4 g_T5q[16*64];         // [kx][q] (c,c,s,s)  th = 2pi q kx/256

// ---------------- k0: tiled weight transpose + tables ---------------------
__global__ void k0_prep(const float* __restrict__ w1re, const float* __restrict__ w1im,
                        const float* __restrict__ w2re, const float* __restrict__ w2im) {
    int blk = blockIdx.x, tid = threadIdx.x;
    if (blk < 256) {
        __shared__ float2 t1[64*33], t2[64*33];
        int io0 = (blk >> 3) * 32, e0 = (blk & 7) * 64;
        int el = tid & 63, iol = tid >> 6;
        int e = e0 + el;
        int ktw = e >> 5, kx = (e >> 1) & 15, kz = e & 1;
        int off = ktw*48 + kx*3 + kz;
        #pragma unroll
        for (int pass = 0; pass < 8; pass++) {
            int il = pass*4 + iol;
            int s = (io0 + il)*768 + off;
            t1[el*33 + il] = make_float2(w1re[s], w1im[s]);
            t2[el*33 + il] = make_float2(w2re[s], w2im[s]);
        }
        __syncthreads();
        int il2 = tid & 31;
        #pragma unroll
        for (int pass = 0; pass < 8; pass++) {
            int el2 = pass*8 + (tid >> 5);
            g_W[(size_t)(e0 + el2)*1024 + io0 + il2]       = t1[el2*33 + il2];
            g_W[(size_t)(e0 + el2 + 512)*1024 + io0 + il2] = t2[el2*33 + il2];
        }
    } else if (blk == 256) {
        for (int i = tid; i < 1024; i += 256) {
            int q = i >> 4, kx = i & 15;
            float s, c; sincospif((float)(q*kx) * (1.0f/128.0f), &s, &c);
            g_T1q[i] = make_float4(c, c, s, s);
        }
    } else if (blk == 257) {
        for (int i = tid; i < 1024; i += 256) {
            int q = i >> 5, kt = i & 31;
            int ktg = kt + ((kt >= 16) ? 96 : 0);
            float s, c; sincospif((float)(q*ktg) * (1.0f/64.0f), &s, &c);
            g_T2[i] = make_float2(c, s);
        }
    } else if (blk == 258) {
        for (int i = tid; i < 1024; i += 256) {
            int kt = i >> 5, q = i & 31;
            int ktg = kt + ((kt >= 16) ? 96 : 0);
            float s, c; sincospif((float)(q*ktg) * (1.0f/64.0f), &s, &c);
            g_T4[i] = make_float2(c, s);
        }
    } else {
        for (int i = tid; i < 1024; i += 256) {
            int kx = i >> 6, q = i & 63;
            float s, c; sincospif((float)(q*kx) * (1.0f/128.0f), &s, &c);
            g_T5q[i] = make_float4(c, c, s, s);
        }
    }
}

// ---------------- kA: fused x-DFT + t-DFT + p-rfft ------------------------
// grid 256 = bi; block 384 = 12 warps = (class 4) x (p 3); lane = (j4, tp8)
// dyn smem: A_sh 6144 f2 (49152 B) + staging 4*1552 u64 (49664 B) = 98816 B
__global__ void __launch_bounds__(384, 2) kA_fwd(const float* __restrict__ x) {
    extern __shared__ float2 smem[];
    float2* A_sh = smem;                 // [kx][p][t] 16*3*128
    u64* SB = (u64*)(smem + 6144);       // staging: 4 buffers x (8*194) u64
    u64* E0 = SB;
    u64* E2 = SB + 1552;
    u64* DA = SB + 3104;
    u64* DB = SB + 4656;
    int bi = blockIdx.x, tid = threadIdx.x;

    int w = tid >> 5, lane = tid & 31;
    int cls = w & 3, p = w >> 2;
    int j = lane >> 3, tp = lane & 7;
    int kx = cls + 4*j;
    const ulonglong2* T1 = (const ulonglong2*)g_T1q;

    // ---- phase 1: x-DFT radix-4, one 16-t chunk at a time ---------------
    for (int chunk = 0; chunk < 8; chunk++) {
        const float* src = x + ((size_t)bi*128 + chunk*16) * 768;
        {   // vectorized staging: 384 items = (tpp 8) x (r4 48)
            int tpp = tid / 48;
            int r4 = (tid - tpp*48) * 4;
            const float* s0 = src + (2*tpp)*768 + r4;
            const float* s1 = s0 + 768;
            float4 a0 = *(const float4*)(s0);
            float4 a1 = *(const float4*)(s0 + 192);
            float4 a2 = *(const float4*)(s0 + 384);
            float4 a3 = *(const float4*)(s0 + 576);
            float4 b0 = *(const float4*)(s1);
            float4 b1 = *(const float4*)(s1 + 192);
            float4 b2 = *(const float4*)(s1 + 384);
            float4 b3 = *(const float4*)(s1 + 576);
            u64 e0v[4], e2v[4], dav[4], dbv[4];
            #define FOLD(jj, xa0, xa1, xa2, xa3, xb0, xb1, xb2, xb3) { \
                float s02a = (xa0) + (xa2), s13a = (xa1) + (xa3);      \
                float s02b = (xb0) + (xb2), s13b = (xb1) + (xb3);      \
                e0v[jj] = pack2(s02a + s13a, s02b + s13b);             \
                e2v[jj] = pack2(s02a - s13a, s02b - s13b);             \
                dav[jj] = pack2((xa0) - (xa2), (xb0) - (xb2));         \
                dbv[jj] = pack2((xa1) - (xa3), (xb1) - (xb3)); }
            FOLD(0, a0.x, a1.x, a2.x, a3.x, b0.x, b1.x, b2.x, b3.x)
            FOLD(1, a0.y, a1.y, a2.y, a3.y, b0.y, b1.y, b2.y, b3.y)
            FOLD(2, a0.z, a1.z, a2.z, a3.z, b0.z, b1.z, b2.z, b3.z)
            FOLD(3, a0.w, a1.w, a2.w, a3.w, b0.w, b1.w, b2.w, b3.w)
            #undef FOLD
            int bx = tpp*194 + r4;
            *(ulonglong2*)&E0[bx]     = make_ulonglong2(e0v[0], e0v[1]);
            *(ulonglong2*)&E0[bx + 2] = make_ulonglong2(e0v[2], e0v[3]);
            *(ulonglong2*)&E2[bx]     = make_ulonglong2(e2v[0], e2v[1]);
            *(ulonglong2*)&E2[bx + 2] = make_ulonglong2(e2v[2], e2v[3]);
            *(ulonglong2*)&DA[bx]     = make_ulonglong2(dav[0], dav[1]);
            *(ulonglong2*)&DA[bx + 2] = make_ulonglong2(dav[2], dav[3]);
            *(ulonglong2*)&DB[bx]     = make_ulonglong2(dbv[0], dbv[1]);
            *(ulonglong2*)&DB[bx + 2] = make_ulonglong2(dbv[2], dbv[3]);
        }
        __syncthreads();
        int t0 = chunk*16 + tp*2;
        if ((cls & 1) == 0) {
            const u64* row = (cls == 0 ? E0 : E2) + tp*194;
            u64 R = 0, I = 0;
            #pragma unroll 16
            for (int q = 0; q < 64; q++) {
                ulonglong2 T = __ldg(T1 + q*16 + kx);
                u64 v = row[q*3 + p];
                ffma2(R, v, T.x);
                ffma2(I, v, T.y);
            }
            float2 r = u2f(R), i = u2f(I);
            *(float4*)(A_sh + (kx*3 + p)*128 + t0) = make_float4(r.x, -i.x, r.y, -i.y);
        } else {
            const u64* ra = DA + tp*194;
            const u64* rb = DB + tp*194;
            u64 RA=0, IA=0, RB=0, IB=0;
            #pragma unroll 16
            for (int q = 0; q < 64; q++) {
                ulonglong2 T = __ldg(T1 + q*16 + kx);
                u64 va = ra[q*3 + p], vb = rb[q*3 + p];
                ffma2(RA, va, T.x);
                ffma2(IA, va, T.y);
                ffma2(RB, vb, T.y);
                ffma2(IB, vb, T.x);
            }
            float sg = (cls == 1) ? -1.f : 1.f;   // class1: b=-d13; class3: b=+d13
            float2 rA = u2f(RA), rB = u2f(RB), iA = u2f(IA), iB = u2f(IB);
            *(float4*)(A_sh + (kx*3 + p)*128 + t0) =
                make_float4(rA.x + sg*rB.x, sg*iB.x - iA.x,
                            rA.y + sg*rB.y, sg*iB.y - iA.y);
        }
        __syncthreads();
    }

    // ---- phase 2: t-DFT radix-4 + p-rfft --------------------------------
    float2* Ys = smem + 6144;     // [kx][(c*3+p)*32+q]  16*384 = 6144 (aliases staging)
    float2* Xt = A_sh;            // aliases dead A_sh    1536
    for (int idx = tid; idx < 1536; idx += 384) {         // class build
        int kxx = idx / 96, r = idx - kxx*96;
        int pp = r >> 5, q = r & 31;
        const float2* Ap = A_sh + kxx*384 + pp*128;
        float2 A0 = Ap[q], A1 = Ap[q + 32], A2 = Ap[q + 64], A3 = Ap[q + 96];
        float Dx = A0.x - A2.x, Dy = A0.y - A2.y;
        float Ex = A1.x - A3.x, Ey = A1.y - A3.y;
        float2* Yk = Ys + kxx*384;
        Yk[(0*3 + pp)*32 + q] = make_float2(A0.x+A1.x+A2.x+A3.x, A0.y+A1.y+A2.y+A3.y);
        Yk[(1*3 + pp)*32 + q] = make_float2(Dx + Ey, Dy - Ex);
        Yk[(2*3 + pp)*32 + q] = make_float2(A0.x-A1.x+A2.x-A3.x, A0.y-A1.y+A2.y-A3.y);
        Yk[(3*3 + pp)*32 + q] = make_float2(Dx - Ey, Dy + Ex);
    }
    __syncthreads();
    for (int idx = tid; idx < 1536; idx += 384) {         // mode dot products
        int kxx = idx / 96, r = idx - kxx*96;
        int kt = r & 31, pp = r >> 5;
        const float2* Yp = Ys + kxx*384 + ((kt & 3)*3 + pp)*32;
        float re = 0.f, im = 0.f;
        #pragma unroll
        for (int q = 0; q < 32; q++) {
            float2 y = Yp[q];
            float2 cs = __ldg(&g_T2[q*32 + kt]);
            re += y.x*cs.x + y.y*cs.y;
            im += y.y*cs.x - y.x*cs.y;
        }
        Xt[(kxx*32 + kt)*3 + pp] = make_float2(re, im);
    }
    __syncthreads();
    for (int idx = tid; idx < 1024; idx += 384) {         // p-rfft + store
        int kxx = idx >> 6, r = idx & 63;
        int kt = r & 31, kz = r >> 5;
        const float2* Xp = Xt + (kxx*32 + kt)*3;
        float2 a0 = Xp[0], a1 = Xp[1], a2 = Xp[2];
        float2 rr;
        if (kz == 0) rr = make_float2(a0.x + a1.x + a2.x, a0.y + a1.y + a2.y);
        else rr = make_float2(a0.x - 0.5f*(a1.x + a2.x) + S3*(a1.y - a2.y),
                              a0.y - 0.5f*(a1.y + a2.y) - S3*(a1.x - a2.x));
        g_X[(size_t)((kt*16 + kxx)*2 + kz)*256 + bi] = rr;
    }
}

// ---------------- k3: per-mode complex GEMM -------------------------------
__global__ void k3_mix() {
    __shared__ float2 Xs[256];
    __shared__ float2 Ws[1024];
    int mode = blockIdx.x, tid = threadIdx.x;
    Xs[tid] = g_X[(size_t)mode*256 + tid];
    const float4* wsrc = (const float4*)(g_W + (size_t)mode*1024);
    float4* wdst = (float4*)Ws;
    wdst[tid]       = wsrc[tid];
    wdst[tid + 256] = wsrc[tid + 256];
    __syncthreads();
    int b = tid >> 5, o = tid & 31;
    float re0=0, im0=0, re1=0, im1=0;
    #pragma unroll
    for (int i = 0; i < 32; i += 2) {
        float2 xv = Xs[b*32 + i];     float2 wv = Ws[i*32 + o];
        re0 += xv.x*wv.x - xv.y*wv.y; im0 += xv.x*wv.y + xv.y*wv.x;
        float2 xq = Xs[b*32 + i + 1]; float2 wq = Ws[(i+1)*32 + o];
        re1 += xq.x*wq.x - xq.y*wq.y; im1 += xq.x*wq.y + xq.y*wq.x;
    }
    int kz = mode & 1, kx = (mode >> 1) & 15, kt = mode >> 5;
    g_Y[(size_t)(((b*32 + o)*16 + kx)*32 + kt)*2 + kz] = make_float2(re0+re1, im0+im1);
}

// ---------------- kB: fused U-build + t-expand + x-expand -----------------
// grid 256 = bo; block 384, 2 blocks/SM
// dyn smem: Y 1024 f2 + U 1536 f2 + Vq 64*49 u64x2 = 20480 + 50176 = 70656 B
__global__ void __launch_bounds__(384, 2) kB_inv(float* __restrict__ out) {
    extern __shared__ float2 smem[];
    float2* Y_sh = smem;                          // [kx*64 + kt*2 + kz]
    float2* U_sh = smem + 1024;                   // [kx*96 + kt*3 + p]
    ulonglong2* Vq = (ulonglong2*)(smem + 2560);  // [pr*49 + kx*3 + p] = (vx01, vy01)
    int bo = blockIdx.x, tid = threadIdx.x;

    // B1: load Y slice
    for (int idx = tid; idx < 512; idx += 384)
        ((float4*)Y_sh)[idx] = ((const float4*)(g_Y + (size_t)bo*1024))[idx];
    __syncthreads();

    // B2: build U
    for (int idx = tid; idx < 1536; idx += 384) {
        int kx = idx / 96, r = idx - kx*96;
        int kt = r & 31, p = r >> 5;
        float2 y0 = Y_sh[kx*64 + kt*2], y1 = Y_sh[kx*64 + kt*2 + 1];
        float wx, wy;                          // 2 * e^{2 pi i p / 3}
        if (p == 0)      { wx = 2.f;  wy = 0.f; }
        else if (p == 1) { wx = -1.f; wy =  2.f*S3; }
        else             { wx = -1.f; wy = -2.f*S3; }
        const float SC = 1.f/98304.f;          // 1/(128*256*3)
        U_sh[kx*96 + kt*3 + p] = make_float2(SC*(y0.x + wx*y1.x - wy*y1.y),
                                             SC*(y0.y + wx*y1.y + wy*y1.x));
    }
    __syncthreads();

    // B3: t-expand radix-4 -> Vq (SoA t-pairs, interleaved 16B entries)
    for (int idx = tid; idx < 1536; idx += 384) {
        int kx = idx / 96, r = idx - kx*96;
        int q = r & 31, p = r >> 5;
        float s0x=0,s0y=0, s1x=0,s1y=0, s2x=0,s2y=0, s3x=0,s3y=0;
        #pragma unroll
        for (int kt = 0; kt < 32; kt++) {
            float2 u = U_sh[kx*96 + kt*3 + p];
            float2 cs = __ldg(&g_T4[kt*32 + q]);
            float tr = u.x*cs.x - u.y*cs.y;
            float ti = u.x*cs.y + u.y*cs.x;
            switch (kt & 3) {
                case 0: s0x += tr; s0y += ti; break;
                case 1: s1x += tr; s1y += ti; break;
                case 2: s2x += tr; s2y += ti; break;
                default: s3x += tr; s3y += ti; break;
            }
        }
        float vr[4], vi[4];
        vr[0] = s0x+s1x+s2x+s3x; vi[0] = s0y+s1y+s2y+s3y;
        vr[1] = s0x-s1y-s2x+s3y; vi[1] = s0y+s1x-s2y-s3x;
        vr[2] = s0x-s1x+s2x-s3x; vi[2] = s0y-s1y+s2y-s3y;
        vr[3] = s0x+s1y-s2x-s3y; vi[3] = s0y-s1x-s2y+s3x;
        int h = q & 1;
        float* base = (float*)Vq;
        #pragma unroll
        for (int m = 0; m < 4; m++) {
            int pr = (q >> 1) + 16*m;
            int e4 = (pr*49 + kx*3 + p)*4;
            base[e4 + h]     = vr[m];
            base[e4 + 2 + h] = vi[m];
        }
    }
    __syncthreads();

    // B4: x-expand radix-4, FFMA2 over t-pairs; thread = (prh, q, p)
    //     pr warp-uniform -> Vq LDS is broadcast; q*3+p lane-consecutive -> coalesced STG
    {
        const ulonglong2* T5 = (const ulonglong2*)g_T5q;
        int ee = tid % 192, prh = tid / 192;
        int q = ee / 3, p = ee - q*3;
        for (int it = 0; it < 32; it++) {
            int pr = prh*32 + it;
            const ulonglong2* vrow = Vq + pr*49 + p;
            u64 A0=0,B0=0, A1=0,B1=0,C1=0,D1=0, A2=0,B2=0, A3=0,B3=0,C3=0,D3=0;
            #pragma unroll
            for (int kx = 0; kx < 16; kx++) {
                ulonglong2 T = __ldg(T5 + kx*64 + q);
                ulonglong2 v = vrow[kx*3];
                switch (kx & 3) {
                    case 0: ffma2(A0, v.x, T.x); ffma2(B0, v.y, T.y); break;
                    case 1: ffma2(A1, v.x, T.x); ffma2(B1, v.y, T.y);
                            ffma2(C1, v.x, T.y); ffma2(D1, v.y, T.x); break;
                    case 2: ffma2(A2, v.x, T.x); ffma2(B2, v.y, T.y); break;
                    default:ffma2(A3, v.x, T.x); ffma2(B3, v.y, T.y);
                            ffma2(C3, v.x, T.y); ffma2(D3, v.y, T.x); break;
                }
            }
            float* r0 = out + ((size_t)bo*128 + pr*2)*768;
            float* r1 = r0 + 768;
            float2 a0 = u2f(A0), b0 = u2f(B0);
            float2 a1 = u2f(A1), b1 = u2f(B1), c1 = u2f(C1), d1 = u2f(D1);
            float2 a2 = u2f(A2), b2 = u2f(B2);
            float2 a3 = u2f(A3), b3 = u2f(B3), c3 = u2f(C3), d3 = u2f(D3);
            #pragma unroll
            for (int h = 0; h < 2; h++) {
                float tr0 = h ? a0.y-b0.y : a0.x-b0.x;
                float tr1 = h ? a1.y-b1.y : a1.x-b1.x;
                float ti1 = h ? c1.y+d1.y : c1.x+d1.x;
                float tr2 = h ? a2.y-b2.y : a2.x-b2.x;
                float tr3 = h ? a3.y-b3.y : a3.x-b3.x;
                float ti3 = h ? c3.y+d3.y : c3.x+d3.x;
                float ev = tr0 + tr2, fv = tr0 - tr2;
                float g1 = tr1 + tr3, dti = ti3 - ti1;
                float* row = h ? r1 : r0;
                row[(q      )*3 + p] = ev + g1;
                row[(q + 64 )*3 + p] = fv + dti;
                row[(q + 128)*3 + p] = ev - g1;
                row[(q + 192)*3 + p] = fv - dti;
            }
        }
    }
}

extern "C" void kernel_launch(void* const* d_in, const int* in_sizes, int n_in,
                              void* d_out, int out_size) {
    const float* x    = (const float*)d_in[0];
    const float* w1re = (const float*)d_in[1];
    const float* w1im = (const float*)d_in[2];
    const float* w2re = (const float*)d_in[3];
    const float* w2im = (const float*)d_in[4];
    float* out = (float*)d_out;

    static int attr_done = 0;
    if (!attr_done) {
        cudaFuncSetAttribute(kA_fwd, cudaFuncAttributeMaxDynamicSharedMemorySize, 98816);
        cudaFuncSetAttribute(kB_inv, cudaFuncAttributeMaxDynamicSharedMemorySize, 70656);
        attr_done = 1;
    }

    k0_prep<<<260, 256>>>(w1re, w1im, w2re, w2im);
    kA_fwd<<<256, 384, 98816>>>(x);
    k3_mix<<<1024, 256>>>();
    kB_inv<<<256, 384, 70656>>>(out);
}

// round 11
// speedup vs baseline: 3.9612x; 1.1991x over previous
#include <cuda_runtime.h>

#define S3 0.86602540378443864676f   // sqrt(3)/2
typedef unsigned long long u64;

__device__ __forceinline__ void ffma2(u64 &d, u64 a, u64 b) {
    asm("fma.rn.f32x2 %0, %1, %2, %0;" : "+l"(d) : "l"(a), "l"(b));
}
__device__ __forceinline__ u64 mul2(u64 a, u64 b) {
    u64 r; asm("mul.rn.f32x2 %0, %1, %2;" : "=l"(r) : "l"(a), "l"(b)); return r;
}
__device__ __forceinline__ float2 u2f(u64 v) {
    float2 f; asm("mov.b64 {%0,%1}, %2;" : "=f"(f.x), "=f"(f.y) : "l"(v)); return f;
}
__device__ __forceinline__ u64 pack2(float lo, float hi) {
    u64 r; asm("mov.b64 %0, {%1,%2};" : "=l"(r) : "f"(lo), "f"(hi)); return r;
}

// ---------------- scratch ----------------
__device__ float2 g_X[1024*256];        // [mode][b*32+i]
__device__ float2 g_W[1024*1024];       // [mode][i*32+o]
__device__ float2 g_Y[8*32*16*32*2];    // [bo][kx][kt][kz]
// twiddle tables
__device__ float4 g_T1q[64*16];         // [q][kx] (c,c,s,s)  th = 2pi q kx/256
__device__ float2 g_T2[32*32];          // [q][kt] (c,s)      ph = 2pi q ktg/128
__device__ float2 g_T4[32*32];          // [kt][q] (c,s)
__device__ float4 g_T5q[16*64];         // [kx][q] (c,c,s,s)  th = 2pi q kx/256

// ---------------- k0: tiled weight transpose + tables ---------------------
__global__ void k0_prep(const float* __restrict__ w1re, const float* __restrict__ w1im,
                        const float* __restrict__ w2re, const float* __restrict__ w2im) {
    int blk = blockIdx.x, tid = threadIdx.x;
    if (blk < 256) {
        __shared__ float2 t1[64*33], t2[64*33];
        int io0 = (blk >> 3) * 32, e0 = (blk & 7) * 64;
        int el = tid & 63, iol = tid >> 6;
        int e = e0 + el;
        int ktw = e >> 5, kx = (e >> 1) & 15, kz = e & 1;
        int off = ktw*48 + kx*3 + kz;
        #pragma unroll
        for (int pass = 0; pass < 8; pass++) {
            int il = pass*4 + iol;
            int s = (io0 + il)*768 + off;
            t1[el*33 + il] = make_float2(w1re[s], w1im[s]);
            t2[el*33 + il] = make_float2(w2re[s], w2im[s]);
        }
        __syncthreads();
        int il2 = tid & 31;
        #pragma unroll
        for (int pass = 0; pass < 8; pass++) {
            int el2 = pass*8 + (tid >> 5);
            g_W[(size_t)(e0 + el2)*1024 + io0 + il2]       = t1[el2*33 + il2];
            g_W[(size_t)(e0 + el2 + 512)*1024 + io0 + il2] = t2[el2*33 + il2];
        }
    } else if (blk == 256) {
        for (int i = tid; i < 1024; i += 256) {
            int q = i >> 4, kx = i & 15;
            float s, c; sincospif((float)(q*kx) * (1.0f/128.0f), &s, &c);
            g_T1q[i] = make_float4(c, c, s, s);
        }
    } else if (blk == 257) {
        for (int i = tid; i < 1024; i += 256) {
            int q = i >> 5, kt = i & 31;
            int ktg = kt + ((kt >= 16) ? 96 : 0);
            float s, c; sincospif((float)(q*ktg) * (1.0f/64.0f), &s, &c);
            g_T2[i] = make_float2(c, s);
        }
    } else if (blk == 258) {
        for (int i = tid; i < 1024; i += 256) {
            int kt = i >> 5, q = i & 31;
            int ktg = kt + ((kt >= 16) ? 96 : 0);
            float s, c; sincospif((float)(q*ktg) * (1.0f/64.0f), &s, &c);
            g_T4[i] = make_float2(c, s);
        }
    } else {
        for (int i = tid; i < 1024; i += 256) {
            int kx = i >> 6, q = i & 63;
            float s, c; sincospif((float)(q*kx) * (1.0f/128.0f), &s, &c);
            g_T5q[i] = make_float4(c, c, s, s);
        }
    }
}

// rotate packed (CC,SS) by (RC,RS):  c' = c*rc - s*rs ; s' = s*rc + c*rs
#define ROT() { u64 t_ = mul2(CC, RC); ffma2(t_, SS, NRS); \
                u64 u_ = mul2(SS, RC); ffma2(u_, CC, RS);  \
                CC = t_; SS = u_; }

// ---------------- kA: fused x-DFT + t-DFT + p-rfft ------------------------
// grid 256 = bi; block 384 = 12 warps = (class 4) x (p 3); lane = (j4, tp8)
// dyn smem: A_sh 6144 f2 (49152 B) + staging 6208 u64 (49664 B) = 98816 B
__global__ void __launch_bounds__(384, 2) kA_fwd(const float* __restrict__ x) {
    extern __shared__ float2 smem[];
    float2* A_sh = smem;                 // [kx][p][t] 16*3*128
    u64* SB  = (u64*)(smem + 6144);
    u64* E0  = SB;                       // 1552
    u64* E2  = SB + 1552;                // 1552
    u64* DAB = SB + 3104;                // 3104 (interleaved {da, db})
    int bi = blockIdx.x, tid = threadIdx.x;

    int w = tid >> 5, lane = tid & 31;
    int cls = w & 3, p = w >> 2;
    int j = lane >> 3, tp = lane & 7;
    int kx = cls + 4*j;
    const ulonglong2* T1 = (const ulonglong2*)g_T1q;

    // per-thread rotator: step angle 2*pi*kx/256 = pi*kx/128
    float rs_, rc_; sincospif((float)kx * (1.0f/128.0f), &rs_, &rc_);
    u64 RC = pack2(rc_, rc_), RS = pack2(rs_, rs_), NRS = pack2(-rs_, -rs_);

    // ---- phase 1: x-DFT radix-4, one 16-t chunk at a time ---------------
    for (int chunk = 0; chunk < 8; chunk++) {
        const float* src = x + ((size_t)bi*128 + chunk*16) * 768;
        {   // vectorized staging: 384 items = (tpp 8) x (r4 48)
            int tpp = tid / 48;
            int r4 = (tid - tpp*48) * 4;
            const float* s0 = src + (2*tpp)*768 + r4;
            const float* s1 = s0 + 768;
            float4 a0 = *(const float4*)(s0);
            float4 a1 = *(const float4*)(s0 + 192);
            float4 a2 = *(const float4*)(s0 + 384);
            float4 a3 = *(const float4*)(s0 + 576);
            float4 b0 = *(const float4*)(s1);
            float4 b1 = *(const float4*)(s1 + 192);
            float4 b2 = *(const float4*)(s1 + 384);
            float4 b3 = *(const float4*)(s1 + 576);
            u64 e0v[4], e2v[4], dav[4], dbv[4];
            #define FOLD(jj, xa0, xa1, xa2, xa3, xb0, xb1, xb2, xb3) { \
                float s02a = (xa0) + (xa2), s13a = (xa1) + (xa3);      \
                float s02b = (xb0) + (xb2), s13b = (xb1) + (xb3);      \
                e0v[jj] = pack2(s02a + s13a, s02b + s13b);             \
                e2v[jj] = pack2(s02a - s13a, s02b - s13b);             \
                dav[jj] = pack2((xa0) - (xa2), (xb0) - (xb2));         \
                dbv[jj] = pack2((xa1) - (xa3), (xb1) - (xb3)); }
            FOLD(0, a0.x, a1.x, a2.x, a3.x, b0.x, b1.x, b2.x, b3.x)
            FOLD(1, a0.y, a1.y, a2.y, a3.y, b0.y, b1.y, b2.y, b3.y)
            FOLD(2, a0.z, a1.z, a2.z, a3.z, b0.z, b1.z, b2.z, b3.z)
            FOLD(3, a0.w, a1.w, a2.w, a3.w, b0.w, b1.w, b2.w, b3.w)
            #undef FOLD
            int bx = tpp*194 + r4;
            *(ulonglong2*)&E0[bx]       = make_ulonglong2(e0v[0], e0v[1]);
            *(ulonglong2*)&E0[bx + 2]   = make_ulonglong2(e0v[2], e0v[3]);
            *(ulonglong2*)&E2[bx]       = make_ulonglong2(e2v[0], e2v[1]);
            *(ulonglong2*)&E2[bx + 2]   = make_ulonglong2(e2v[2], e2v[3]);
            *(ulonglong2*)&DAB[2*bx]     = make_ulonglong2(dav[0], dbv[0]);
            *(ulonglong2*)&DAB[2*bx + 2] = make_ulonglong2(dav[1], dbv[1]);
            *(ulonglong2*)&DAB[2*bx + 4] = make_ulonglong2(dav[2], dbv[2]);
            *(ulonglong2*)&DAB[2*bx + 6] = make_ulonglong2(dav[3], dbv[3]);
        }
        __syncthreads();
        int t0 = chunk*16 + tp*2;
        if ((cls & 1) == 0) {
            const u64* row = (cls == 0 ? E0 : E2) + tp*194;
            u64 R = 0, I = 0;
            #pragma unroll
            for (int g = 0; g < 4; g++) {
                ulonglong2 T = __ldg(T1 + g*256 + kx);   // exact refresh at q=16g
                u64 CC = T.x, SS = T.y;
                #pragma unroll
                for (int qq = 0; qq < 16; qq++) {
                    u64 v = row[(g*16 + qq)*3 + p];
                    ffma2(R, v, CC); ffma2(I, v, SS);
                    if (qq != 15) ROT();
                }
            }
            float2 r = u2f(R), i = u2f(I);
            *(float4*)(A_sh + (kx*3 + p)*128 + t0) = make_float4(r.x, -i.x, r.y, -i.y);
        } else {
            const ulonglong2* rab = (const ulonglong2*)DAB + tp*194;
            u64 RA=0, IA=0, RB=0, IB=0;
            #pragma unroll
            for (int g = 0; g < 4; g++) {
                ulonglong2 T = __ldg(T1 + g*256 + kx);
                u64 CC = T.x, SS = T.y;
                #pragma unroll
                for (int qq = 0; qq < 16; qq++) {
                    ulonglong2 vab = rab[(g*16 + qq)*3 + p];
                    ffma2(RA, vab.x, CC);
                    ffma2(IA, vab.x, SS);
                    ffma2(RB, vab.y, SS);
                    ffma2(IB, vab.y, CC);
                    if (qq != 15) ROT();
                }
            }
            float sg = (cls == 1) ? -1.f : 1.f;   // class1: b=-d13; class3: b=+d13
            float2 rA = u2f(RA), rB = u2f(RB), iA = u2f(IA), iB = u2f(IB);
            *(float4*)(A_sh + (kx*3 + p)*128 + t0) =
                make_float4(rA.x + sg*rB.x, sg*iB.x - iA.x,
                            rA.y + sg*rB.y, sg*iB.y - iA.y);
        }
        __syncthreads();
    }

    // ---- phase 2: t-DFT radix-4 + p-rfft --------------------------------
    float2* Ys = smem + 6144;     // 16*384, aliases staging
    float2* Xt = A_sh;            // aliases dead A_sh
    for (int idx = tid; idx < 1536; idx += 384) {         // class build
        int kxx = idx / 96, r = idx - kxx*96;
        int pp = r >> 5, q = r & 31;
        const float2* Ap = A_sh + kxx*384 + pp*128;
        float2 A0 = Ap[q], A1 = Ap[q + 32], A2 = Ap[q + 64], A3 = Ap[q + 96];
        float Dx = A0.x - A2.x, Dy = A0.y - A2.y;
        float Ex = A1.x - A3.x, Ey = A1.y - A3.y;
        float2* Yk = Ys + kxx*384;
        Yk[(0*3 + pp)*32 + q] = make_float2(A0.x+A1.x+A2.x+A3.x, A0.y+A1.y+A2.y+A3.y);
        Yk[(1*3 + pp)*32 + q] = make_float2(Dx + Ey, Dy - Ex);
        Yk[(2*3 + pp)*32 + q] = make_float2(A0.x-A1.x+A2.x-A3.x, A0.y-A1.y+A2.y-A3.y);
        Yk[(3*3 + pp)*32 + q] = make_float2(Dx - Ey, Dy + Ex);
    }
    __syncthreads();
    for (int idx = tid; idx < 1536; idx += 384) {         // mode dot products
        int kxx = idx / 96, r = idx - kxx*96;
        int kt = r & 31, pp = r >> 5;
        const float2* Yp = Ys + kxx*384 + ((kt & 3)*3 + pp)*32;
        float re = 0.f, im = 0.f;
        #pragma unroll
        for (int q = 0; q < 32; q++) {
            float2 y = Yp[q];
            float2 cs = __ldg(&g_T2[q*32 + kt]);
            re += y.x*cs.x + y.y*cs.y;
            im += y.y*cs.x - y.x*cs.y;
        }
        Xt[(kxx*32 + kt)*3 + pp] = make_float2(re, im);
    }
    __syncthreads();
    for (int idx = tid; idx < 1024; idx += 384) {         // p-rfft + store
        int kxx = idx >> 6, r = idx & 63;
        int kt = r & 31, kz = r >> 5;
        const float2* Xp = Xt + (kxx*32 + kt)*3;
        float2 a0 = Xp[0], a1 = Xp[1], a2 = Xp[2];
        float2 rr;
        if (kz == 0) rr = make_float2(a0.x + a1.x + a2.x, a0.y + a1.y + a2.y);
        else rr = make_float2(a0.x - 0.5f*(a1.x + a2.x) + S3*(a1.y - a2.y),
                              a0.y - 0.5f*(a1.y + a2.y) - S3*(a1.x - a2.x));
        g_X[(size_t)((kt*16 + kxx)*2 + kz)*256 + bi] = rr;
    }
}

// ---------------- k3: per-mode complex GEMM -------------------------------
__global__ void k3_mix() {
    __shared__ float2 Xs[256];
    __shared__ float2 Ws[1024];
    int mode = blockIdx.x, tid = threadIdx.x;
    Xs[tid] = g_X[(size_t)mode*256 + tid];
    const float4* wsrc = (const float4*)(g_W + (size_t)mode*1024);
    float4* wdst = (float4*)Ws;
    wdst[tid]       = wsrc[tid];
    wdst[tid + 256] = wsrc[tid + 256];
    __syncthreads();
    int b = tid >> 5, o = tid & 31;
    float re0=0, im0=0, re1=0, im1=0;
    #pragma unroll
    for (int i = 0; i < 32; i += 2) {
        float2 xv = Xs[b*32 + i];     float2 wv = Ws[i*32 + o];
        re0 += xv.x*wv.x - xv.y*wv.y; im0 += xv.x*wv.y + xv.y*wv.x;
        float2 xq = Xs[b*32 + i + 1]; float2 wq = Ws[(i+1)*32 + o];
        re1 += xq.x*wq.x - xq.y*wq.y; im1 += xq.x*wq.y + xq.y*wq.x;
    }
    int kz = mode & 1, kx = (mode >> 1) & 15, kt = mode >> 5;
    g_Y[(size_t)(((b*32 + o)*16 + kx)*32 + kt)*2 + kz] = make_float2(re0+re1, im0+im1);
}

// ---------------- kB: fused U-build + t-expand + x-expand -----------------
// grid 256 = bo; block 384, 2 blocks/SM
// dyn smem (f2 units): Y 1024 | U 1536 | Vq 6272 | Tsh 512 | T4sh 1024 = 10368 f2 = 82944 B
__global__ void __launch_bounds__(384, 2) kB_inv(float* __restrict__ out) {
    extern __shared__ float2 smem[];
    float2* Y_sh = smem;                          // [kx*64 + kt*2 + kz]
    float2* U_sh = smem + 1024;                   // [kx*96 + kt*3 + p]
    ulonglong2* Vq = (ulonglong2*)(smem + 2560);  // [pr*49 + kx*3 + p] = (vx01, vy01)
    ulonglong2* Tsh = (ulonglong2*)(smem + 8832); // [c-1][q] c=1..4  (cc,ss packed)
    float2* T4sh = smem + 9344;                   // copy of g_T4
    int bo = blockIdx.x, tid = threadIdx.x;

    // B1: load Y slice + stage twiddle tables
    for (int idx = tid; idx < 512; idx += 384)
        ((float4*)Y_sh)[idx] = ((const float4*)(g_Y + (size_t)bo*1024))[idx];
    for (int idx = tid; idx < 256; idx += 384)
        Tsh[idx] = ((const ulonglong2*)g_T5q)[64 + idx];       // rows kx=1..4
    for (int idx = tid; idx < 1024; idx += 384)
        T4sh[idx] = g_T4[idx];
    __syncthreads();

    // B2: build U
    for (int idx = tid; idx < 1536; idx += 384) {
        int kx = idx / 96, r = idx - kx*96;
        int kt = r & 31, p = r >> 5;
        float2 y0 = Y_sh[kx*64 + kt*2], y1 = Y_sh[kx*64 + kt*2 + 1];
        float wx, wy;                          // 2 * e^{2 pi i p / 3}
        if (p == 0)      { wx = 2.f;  wy = 0.f; }
        else if (p == 1) { wx = -1.f; wy =  2.f*S3; }
        else             { wx = -1.f; wy = -2.f*S3; }
        const float SC = 1.f/98304.f;          // 1/(128*256*3)
        U_sh[kx*96 + kt*3 + p] = make_float2(SC*(y0.x + wx*y1.x - wy*y1.y),
                                             SC*(y0.y + wx*y1.y + wy*y1.x));
    }
    __syncthreads();

    // B3: t-expand radix-4 -> Vq
    for (int idx = tid; idx < 1536; idx += 384) {
        int kx = idx / 96, r = idx - kx*96;
        int q = r & 31, p = r >> 5;
        float s0x=0,s0y=0, s1x=0,s1y=0, s2x=0,s2y=0, s3x=0,s3y=0;
        #pragma unroll
        for (int kt = 0; kt < 32; kt++) {
            float2 u = U_sh[kx*96 + kt*3 + p];
            float2 cs = T4sh[kt*32 + q];
            float tr = u.x*cs.x - u.y*cs.y;
            float ti = u.x*cs.y + u.y*cs.x;
            switch (kt & 3) {
                case 0: s0x += tr; s0y += ti; break;
                case 1: s1x += tr; s1y += ti; break;
                case 2: s2x += tr; s2y += ti; break;
                default: s3x += tr; s3y += ti; break;
            }
        }
        float vr[4], vi[4];
        vr[0] = s0x+s1x+s2x+s3x; vi[0] = s0y+s1y+s2y+s3y;
        vr[1] = s0x-s1y-s2x+s3y; vi[1] = s0y+s1x-s2y-s3x;
        vr[2] = s0x-s1x+s2x-s3x; vi[2] = s0y-s1y+s2y-s3y;
        vr[3] = s0x+s1y-s2x-s3y; vi[3] = s0y-s1x-s2y+s3x;
        int h = q & 1;
        float* base = (float*)Vq;
        #pragma unroll
        for (int m = 0; m < 4; m++) {
            int pr = (q >> 1) + 16*m;
            int e4 = (pr*49 + kx*3 + p)*4;
            base[e4 + h]     = vr[m];
            base[e4 + 2 + h] = vi[m];
        }
    }
    __syncthreads();

    // B4: x-expand radix-4 via Horner (no in-loop twiddle loads)
    {
        int ee = tid % 192, prh = tid / 192;
        int q = ee / 3, p = ee - q*3;
        // hoisted per-thread constants
        ulonglong2 Rv = Tsh[192 + q];             // kx=4 row: phi = pi q/32
        u64 RC = Rv.x, RS = Rv.y;
        float2 rsf = u2f(RS);
        u64 NRS = pack2(-rsf.x, -rsf.y);
        float tc1 = u2f(Tsh[q].x).x,       ts1 = u2f(Tsh[q].y).x;
        float tc2 = u2f(Tsh[64 + q].x).x,  ts2 = u2f(Tsh[64 + q].y).x;
        float tc3 = u2f(Tsh[128 + q].x).x, ts3 = u2f(Tsh[128 + q].y).x;

        for (int it = 0; it < 32; it++) {
            int pr = prh*32 + it;
            const ulonglong2* vrow = Vq + pr*49 + p;
            u64 W0x, W0y, W1x, W1y, W2x, W2y, W3x, W3y;
            { ulonglong2 v = vrow[12*3]; W0x = v.x; W0y = v.y; }
            { ulonglong2 v = vrow[13*3]; W1x = v.x; W1y = v.y; }
            { ulonglong2 v = vrow[14*3]; W2x = v.x; W2y = v.y; }
            { ulonglong2 v = vrow[15*3]; W3x = v.x; W3y = v.y; }
            #define HSTEP(c, jj) { \
                ulonglong2 v = vrow[((c) + 4*(jj))*3]; \
                u64 t_ = v.x; ffma2(t_, W##c##x, RC); ffma2(t_, W##c##y, NRS); \
                u64 u_ = v.y; ffma2(u_, W##c##x, RS); ffma2(u_, W##c##y, RC);  \
                W##c##x = t_; W##c##y = u_; }
            HSTEP(0, 2) HSTEP(1, 2) HSTEP(2, 2) HSTEP(3, 2)
            HSTEP(0, 1) HSTEP(1, 1) HSTEP(2, 1) HSTEP(3, 1)
            HSTEP(0, 0) HSTEP(1, 0) HSTEP(2, 0) HSTEP(3, 0)
            #undef HSTEP
            float2 W0xf = u2f(W0x);
            float2 W1xf = u2f(W1x), W1yf = u2f(W1y);
            float2 W2xf = u2f(W2x), W2yf = u2f(W2y);
            float2 W3xf = u2f(W3x), W3yf = u2f(W3y);
            float* r0 = out + ((size_t)bo*128 + pr*2)*768;
            float* r1 = r0 + 768;
            #pragma unroll
            for (int h = 0; h < 2; h++) {
                float w0x = h ? W0xf.y : W0xf.x;
                float w1x = h ? W1xf.y : W1xf.x, w1y = h ? W1yf.y : W1yf.x;
                float w2x = h ? W2xf.y : W2xf.x, w2y = h ? W2yf.y : W2yf.x;
                float w3x = h ? W3xf.y : W3xf.x, w3y = h ? W3yf.y : W3yf.x;
                float tr0 = w0x;
                float tr1 = w1x*tc1 - w1y*ts1;
                float ti1 = w1x*ts1 + w1y*tc1;
                float tr2 = w2x*tc2 - w2y*ts2;
                float tr3 = w3x*tc3 - w3y*ts3;
                float ti3 = w3x*ts3 + w3y*tc3;
                float ev = tr0 + tr2, fv = tr0 - tr2;
                float g1 = tr1 + tr3, dti = ti3 - ti1;
                float* row = h ? r1 : r0;
                row[(q      )*3 + p] = ev + g1;
                row[(q + 64 )*3 + p] = fv + dti;
                row[(q + 128)*3 + p] = ev - g1;
                row[(q + 192)*3 + p] = fv - dti;
            }
        }
    }
}

extern "C" void kernel_launch(void* const* d_in, const int* in_sizes, int n_in,
                              void* d_out, int out_size) {
    const float* x    = (const float*)d_in[0];
    const float* w1re = (const float*)d_in[1];
    const float* w1im = (const float*)d_in[2];
    const float* w2re = (const float*)d_in[3];
    const float* w2im = (const float*)d_in[4];
    float* out = (float*)d_out;

    static int attr_done = 0;
    if (!attr_done) {
        cudaFuncSetAttribute(kA_fwd, cudaFuncAttributeMaxDynamicSharedMemorySize, 98816);
        cudaFuncSetAttribute(kB_inv, cudaFuncAttributeMaxDynamicSharedMemorySize, 82944);
        attr_done = 1;
    }

    k0_prep<<<260, 256>>>(w1re, w1im, w2re, w2im);
    kA_fwd<<<256, 384, 98816>>>(x);
    k3_mix<<<1024, 256>>>();
    kB_inv<<<256, 384, 82944>>>(out);
}